// round 13
// baseline (speedup 1.0000x reference)
#include <cuda_runtime.h>
#include <cuda_fp16.h>
#include <mma.h>
#include <math.h>
#include <cstdint>

using namespace nvcuda;

static constexpr int BATCH = 8;
static constexpr int C     = 256;
static constexpr int HH    = 128;
static constexpr int WWID  = 128;
static constexpr int NWIN  = 512;
static constexpr int T     = 256;
static constexpr int HEADS = 8;
static constexpr int HD    = 32;
static constexpr int MTOK  = NWIN * T;  // 131072

// ---------------- scratch ----------------
__device__ __align__(16) __half g_qh  [(size_t)MTOK * C];   // [win][h][t][e]
__device__ __align__(16) __half g_kh  [(size_t)MTOK * C];
__device__ __align__(16) __half g_vh  [(size_t)MTOK * C];
__device__ __align__(16) __half g_ctx_h[(size_t)MTOK * C];  // [win][t][h*32+e]
__device__ __align__(16) __half g_wqkv_h[768 * 256];
__device__ __align__(16) __half g_wout_h[256 * 256];

__device__ __forceinline__ uint32_t packh2(float lo, float hi) {
    __half2 h = __floats2half2_rn(lo, hi);
    return *reinterpret_cast<uint32_t*>(&h);
}
__device__ __forceinline__ uint32_t ex2h2(uint32_t a) {
    uint32_t d;
    asm("ex2.approx.f16x2 %0, %1;" : "=r"(d) : "r"(a));
    return d;
}
__device__ __forceinline__ uint32_t smem_u32(const void* p) {
    return (uint32_t)__cvta_generic_to_shared(p);
}
__device__ __forceinline__ void cp16(uint32_t dst, const void* src) {
    asm volatile("cp.async.cg.shared.global [%0], [%1], 16;" :: "r"(dst), "l"(src));
}
#define CP_COMMIT() asm volatile("cp.async.commit_group;")
#define CP_WAIT(n)  asm volatile("cp.async.wait_group %0;" :: "n"(n))

__device__ __forceinline__ void mma_f16(float* d,
        uint32_t a0, uint32_t a1, uint32_t a2, uint32_t a3,
        uint32_t b0, uint32_t b1) {
    asm volatile("mma.sync.aligned.m16n8k16.row.col.f32.f16.f16.f32 "
        "{%0,%1,%2,%3}, {%4,%5,%6,%7}, {%8,%9}, {%0,%1,%2,%3};"
        : "+f"(d[0]), "+f"(d[1]), "+f"(d[2]), "+f"(d[3])
        : "r"(a0), "r"(a1), "r"(a2), "r"(a3), "r"(b0), "r"(b1));
}
__device__ __forceinline__ void ldsm_x4(uint32_t* r, uint32_t addr) {
    asm volatile("ldmatrix.sync.aligned.m8n8.x4.shared.b16 {%0,%1,%2,%3}, [%4];"
        : "=r"(r[0]), "=r"(r[1]), "=r"(r[2]), "=r"(r[3]) : "r"(addr));
}
__device__ __forceinline__ void ldsm_x4_t(uint32_t* r, uint32_t addr) {
    asm volatile("ldmatrix.sync.aligned.m8n8.x4.trans.shared.b16 {%0,%1,%2,%3}, [%4];"
        : "=r"(r[0]), "=r"(r[1]), "=r"(r[2]), "=r"(r[3]) : "r"(addr));
}

// ---------------- kernel 0: weight conversion ----------------
__global__ void k_cvtw(const float* __restrict__ wqkv, const float* __restrict__ wout) {
    int i = blockIdx.x * 256 + threadIdx.x;
    if (i < 768 * 256) g_wqkv_h[i] = __float2half(wqkv[i]);
    if (i < 256 * 256) g_wout_h[i] = __float2half(wout[i]);
}

// ---------------- kernel 1: fused LN + QKV projection ----------------
// One CTA per 128-token half-window. A^T resident in smem ([ch][tok] fp16,
// LDT=136). LN computed in-smem, then 6 N-blocks of raw m16n8k16 GEMM with
// B streamed through a 2-stage cp.async ring. Register epilogue scatters
// q/k/v (q pre-scaled by 1/sqrt(32)*log2e).
__global__ __launch_bounds__(256, 2) void k_lnqkv(const float* __restrict__ x,
                                                  const float* __restrict__ lw,
                                                  const float* __restrict__ lb,
                                                  const float* __restrict__ bias) {
    constexpr int LDT = 136;          // halves per ch-row (128 tok + pad)
    constexpr int LDB = 72;           // halves per B row (64 + pad)
    constexpr int BSTG = 128 * LDB;   // 9216 halves per B stage
    constexpr int NBLK = 6;           // 768 / 128
    constexpr int NSTAGES = NBLK * 4; // 24 k-stages of 64

    extern __shared__ char smc[];
    __half* At   = (__half*)smc;                     // 256*136*2 = 69632
    __half* ring = (__half*)(smc + 69632);           // 2*9216*2  = 36864
    float*  lws  = (float*)(smc + 106496);           // 1024
    float*  lbs  = (float*)(smc + 107520);           // 1024
    float*  smu  = (float*)(smc + 108544);           // 512
    float*  srs  = (float*)(smc + 109056);           // 512
    float*  prt  = (float*)(smc + 109568);           // 2048
    // total 111616

    int tid = threadIdx.x;
    int lane = tid & 31;
    int wid = tid >> 5;
    int wmi = wid & 1;        // 2 M-warps (64 rows each)
    int wni = wid >> 1;       // 4 N-warps (32 cols each)

    int gm0 = blockIdx.x * 128;
    int win = gm0 >> 8;
    int halfb = (gm0 >> 7) & 1;
    int b  = win >> 6;
    int wr = (win >> 3) & 7;
    int wc = win & 7;

    // ---- Phase L: load x (fp32) -> At [ch][tok] fp16 ----
    {
        int cl = tid >> 3;      // 0..31 channel-in-chunk
        int ti = tid & 7;       // 0..7 token row in half-window
        #pragma unroll
        for (int chunk = 0; chunk < 8; chunk++) {
            int ch = chunk * 32 + cl;
            const float* gp = x + (size_t)((b * C + ch) * HH + wr * 16 + halfb * 8 + ti) * WWID
                              + wc * 16;
            #pragma unroll
            for (int f4 = 0; f4 < 4; f4++) {
                float4 v = *(const float4*)(gp + f4 * 4);
                *(uint2*)&At[ch * LDT + ti * 16 + f4 * 4] =
                    make_uint2(packh2(v.x, v.y), packh2(v.z, v.w));
            }
        }
    }
    // prefetch first two B stages (independent of At) + stage lw/lb
    auto stageB = [&](int s) {
        int nb = s >> 2, kbi = s & 3;
        __half* Bs = ring + (s & 1) * BSTG;
        const __half* Bg = g_wqkv_h + (size_t)(nb * 128) * 256 + kbi * 64;
        #pragma unroll
        for (int r = 0; r < 4; r++) {
            int i = (r * 256 + tid) * 8;
            int n = i >> 6, k = i & 63;
            cp16(smem_u32(&Bs[n * LDB + k]), Bg + (size_t)n * 256 + k);
        }
    };
    stageB(0); CP_COMMIT();
    stageB(1); CP_COMMIT();
    lws[tid] = lw[tid];
    lbs[tid] = lb[tid];
    __syncthreads();   // At visible to all

    // ---- Phase S: LN stats (two threads per token) ----
    {
        int t = tid & 127, hseg = tid >> 7;
        float s = 0.f, s2 = 0.f;
        int ch0 = hseg * 128;
        #pragma unroll 8
        for (int i = 0; i < 128; i++) {
            float v = __half2float(At[(ch0 + i) * LDT + t]);
            s += v; s2 += v * v;
        }
        prt[2 * tid] = s;
        prt[2 * tid + 1] = s2;
    }
    __syncthreads();
    if (tid < 128) {
        float s  = prt[2 * tid]     + prt[2 * (tid + 128)];
        float s2 = prt[2 * tid + 1] + prt[2 * (tid + 128) + 1];
        float mu  = s * (1.f / C);
        float var = s2 * (1.f / C) - mu * mu;
        smu[tid] = mu;
        srs[tid] = rsqrtf(var + 1e-5f);
    }
    __syncthreads();

    // ---- Phase N: normalize in place ----
    {
        int t = tid & 127, hseg = tid >> 7;
        float mu = smu[t], rs = srs[t];
        int ch0 = hseg * 128;
        #pragma unroll 8
        for (int i = 0; i < 128; i++) {
            int ch = ch0 + i;
            float v = __half2float(At[ch * LDT + t]);
            At[ch * LDT + t] = __float2half((v - mu) * rs * lws[ch] + lbs[ch]);
        }
    }
    CP_WAIT(0);
    __syncthreads();   // At normalized + B stages 0,1 ready

    // ---- Mainloop: 6 N-blocks x 4 k-stages ----
    uint32_t at_base = smem_u32(At);
    // A frag lane geometry (col-major A via ldmatrix.trans)
    int a_tok = wmi * 64 + ((lane >> 3) & 1) * 8;         // + fm*16
    int a_ch  = (lane & 7) + ((lane >> 4) & 1) * 8;       // + k
    // B frag lane geometry
    int b_row = wni * 32 + ((lane >> 4) & 1) * 8 + (lane & 7);  // + ntp*16
    int b_kl  = ((lane >> 3) & 1) * 8;                           // + kk*16

    int g = lane >> 2, c = lane & 3;

    float cf[4][4][4];
    #pragma unroll
    for (int fm = 0; fm < 4; fm++)
        #pragma unroll
        for (int nt = 0; nt < 4; nt++)
            #pragma unroll
            for (int e = 0; e < 4; e++) cf[fm][nt][e] = 0.f;

    #pragma unroll 1
    for (int nb = 0; nb < NBLK; nb++) {
        #pragma unroll
        for (int kbi = 0; kbi < 4; kbi++) {
            int s = nb * 4 + kbi;
            __half* dummy = ring + (s & 1) * BSTG;
            uint32_t bs_base = smem_u32(dummy);
            #pragma unroll
            for (int kk = 0; kk < 4; kk++) {
                int k = kbi * 64 + kk * 16;
                uint32_t af[4][4];
                #pragma unroll
                for (int fm = 0; fm < 4; fm++)
                    ldsm_x4_t(af[fm], at_base + 2 * ((a_ch + k) * LDT + a_tok + fm * 16));
                uint32_t bf[4][2];
                #pragma unroll
                for (int ntp = 0; ntp < 2; ntp++) {
                    uint32_t tmp[4];
                    ldsm_x4(tmp, bs_base + 2 * ((b_row + ntp * 16) * LDB + b_kl + kk * 16));
                    bf[ntp * 2][0] = tmp[0]; bf[ntp * 2][1] = tmp[1];
                    bf[ntp * 2 + 1][0] = tmp[2]; bf[ntp * 2 + 1][1] = tmp[3];
                }
                #pragma unroll
                for (int fm = 0; fm < 4; fm++)
                    #pragma unroll
                    for (int nt = 0; nt < 4; nt++)
                        mma_f16(cf[fm][nt], af[fm][0], af[fm][1], af[fm][2], af[fm][3],
                                bf[nt][0], bf[nt][1]);
            }
            __syncthreads();                    // all warps done with buf s&1
            if (s + 2 < NSTAGES) { stageB(s + 2); CP_COMMIT(); }
            if (s + 1 < NSTAGES) { CP_WAIT(1); } else { CP_WAIT(0); }
            __syncthreads();
        }

        // ---- register epilogue for this N-block ----
        int n0 = nb * 128;
        #pragma unroll
        for (int nt = 0; nt < 4; nt++) {
            int col = n0 + wni * 32 + nt * 8 + 2 * c;
            float2 bb = *(const float2*)&bias[col];
            int part = col >> 8;
            int d = col & 255;
            int hh = d >> 5, e = d & 31;
            float scale = (part == 0) ? 0.25505697382625574f : 1.f;  // 1/sqrt(32)*log2e
            __half* dst = (part == 0) ? g_qh : (part == 1) ? g_kh : g_vh;
            #pragma unroll
            for (int fm = 0; fm < 4; fm++) {
                int r0 = gm0 + wmi * 64 + fm * 16 + g;
                float v00 = (cf[fm][nt][0] + bb.x) * scale;
                float v01 = (cf[fm][nt][1] + bb.y) * scale;
                float v10 = (cf[fm][nt][2] + bb.x) * scale;
                float v11 = (cf[fm][nt][3] + bb.y) * scale;
                size_t o0 = ((size_t)((r0 >> 8) * HEADS + hh) * T + (r0 & 255)) * HD + e;
                size_t o1 = o0 + 8 * (size_t)HD;   // row r0+8
                *(uint32_t*)&dst[o0] = packh2(v00, v01);
                *(uint32_t*)&dst[o1] = packh2(v10, v11);
                cf[fm][nt][0] = 0.f; cf[fm][nt][1] = 0.f;
                cf[fm][nt][2] = 0.f; cf[fm][nt][3] = 0.f;
            }
        }
    }
}

// ---------------- kernel 2: out projection (wmma, fused reverse+residual) --
__global__ __launch_bounds__(256, 2) void k_outproj(const float* __restrict__ bias,
                                                    const float* __restrict__ x,
                                                    float* __restrict__ out) {
    constexpr int BM = 128, BN = 128, BK = 64, WM = 64, WN = 32, KDIM = 256;
    constexpr int WARPS_M = BM / WM;
    constexpr int NT = 256;
    constexpr int LDA = BK + 8;
    constexpr int LDB = BK + 8;
    constexpr int FM = WM / 16, FN = WN / 16;
    constexpr int ASTG = BM * LDA;
    constexpr int STG  = 2 * ASTG;
    constexpr int NS   = 3;
    constexpr int KT   = KDIM / BK;

    extern __shared__ float smf[];
    __half* smh = (__half*)smf;

    int tid = threadIdx.x;
    const __half* A    = g_ctx_h;
    const __half* Bext = g_wout_h;
    int m0 = blockIdx.y * BM;
    int n0 = blockIdx.x * BN;
    int wi = tid >> 5;
    int wmi = wi % WARPS_M;
    int wni = wi / WARPS_M;

    wmma::fragment<wmma::accumulator, 16, 16, 16, float> cf[FM][FN];
    #pragma unroll
    for (int fm = 0; fm < FM; fm++)
        #pragma unroll
        for (int fn = 0; fn < FN; fn++)
            wmma::fill_fragment(cf[fm][fn], 0.f);

    auto stageAB = [&](int kb, int s) {
        __half* As = smh + s * STG;
        __half* Bs = As + ASTG;
        #pragma unroll
        for (int r = 0; r < BM * BK / (NT * 8); r++) {
            int i = (r * NT + tid) * 8;
            int m = i / BK, k = i % BK;
            cp16(smem_u32(&As[m * LDA + k]), &A[(size_t)(m0 + m) * KDIM + kb + k]);
        }
        #pragma unroll
        for (int r = 0; r < BN * BK / (NT * 8); r++) {
            int i = (r * NT + tid) * 8;
            int n = i / BK, k = i % BK;
            cp16(smem_u32(&Bs[n * LDB + k]), &Bext[(size_t)(n0 + n) * KDIM + kb + k]);
        }
    };

    stageAB(0, 0); CP_COMMIT();
    stageAB(BK, 1); CP_COMMIT();
    CP_WAIT(1);
    __syncthreads();

    #pragma unroll
    for (int kbi = 0; kbi < KT; kbi++) {
        __half* As = smh + (kbi % NS) * STG;
        __half* Bs = As + ASTG;
        #pragma unroll
        for (int kk = 0; kk < BK; kk += 16) {
            wmma::fragment<wmma::matrix_a, 16, 16, 16, __half, wmma::row_major> af[FM];
            #pragma unroll
            for (int fm = 0; fm < FM; fm++)
                wmma::load_matrix_sync(af[fm], &As[(wmi * WM + fm * 16) * LDA + kk], LDA);
            #pragma unroll
            for (int fn = 0; fn < FN; fn++) {
                wmma::fragment<wmma::matrix_b, 16, 16, 16, __half, wmma::col_major> bf;
                wmma::load_matrix_sync(bf, &Bs[(wni * WN + fn * 16) * LDB + kk], LDB);
                #pragma unroll
                for (int fm = 0; fm < FM; fm++)
                    wmma::mma_sync(cf[fm][fn], af[fm], bf, cf[fm][fn]);
            }
        }
        if (kbi + NS - 1 < KT) {
            stageAB((kbi + NS - 1) * BK, (kbi + NS - 1) % NS);
            CP_COMMIT();
            CP_WAIT(1);
        } else {
            CP_WAIT(0);
        }
        __syncthreads();
    }

    // fused bias + residual + window reverse; Cs col-major [channel][token]
    constexpr int LDCT = BM + 4;
    float* Cs = smf;
    #pragma unroll
    for (int fm = 0; fm < FM; fm++)
        #pragma unroll
        for (int fn = 0; fn < FN; fn++)
            wmma::store_matrix_sync(&Cs[(wni * WN + fn * 16) * LDCT + wmi * WM + fm * 16],
                                    cf[fm][fn], LDCT, wmma::mem_col_major);
    __syncthreads();
    int n_win = m0 >> 8;
    int halfb = (m0 >> 7) & 1;
    int b  = n_win >> 6;
    int wr = (n_win >> 3) & 7;
    int wc = n_win & 7;
    #pragma unroll
    for (int r = 0; r < BM * BN / (NT * 4); r++) {
        int idx = r * NT + tid;
        int f4 = idx & 3;
        int ti = (idx >> 2) & 7;
        int cl = idx >> 5;
        int gn = n0 + cl;
        int tok = ti * 16 + f4 * 4;
        float4 v = *(float4*)&Cs[cl * LDCT + tok];
        float bb = bias[gn];
        size_t off = ((size_t)(b * C + gn) * HH + wr * 16 + halfb * 8 + ti) * WWID
                   + wc * 16 + f4 * 4;
        float4 xr = *(const float4*)&x[off];
        float4 o_;
        o_.x = xr.x + v.x + bb;
        o_.y = xr.y + v.y + bb;
        o_.z = xr.z + v.z + bb;
        o_.w = xr.w + v.w + bb;
        *(float4*)&out[off] = o_;
    }
}

// ---------------- fused flash attention (f16x2 exp, l via ones-MMA) -------
__global__ __launch_bounds__(256, 2) void k_attn2() {
    constexpr int LDK = 40;    // halves
    constexpr int LDV = 264;   // halves
    extern __shared__ __half smh[];
    __half* Ks = smh;                 // 256*40
    __half* Vt = smh + 256 * LDK;     // 32*264

    int bz   = blockIdx.x >> 1;
    int halfb = blockIdx.x & 1;
    const __half* Q = g_qh + (size_t)bz * T * HD;
    const __half* K = g_kh + (size_t)bz * T * HD;
    const __half* V = g_vh + (size_t)bz * T * HD;
    int tid = threadIdx.x, wi = tid >> 5, lane = tid & 31;
    int g = lane >> 2, c = lane & 3;

    #pragma unroll
    for (int it = 0; it < 8; it++) {
        int i = it * 256 + tid;
        int row = i >> 3, c4 = (i & 7) * 4;
        *(uint2*)&Ks[row * LDK + c4] = *(const uint2*)&K[row * HD + c4];
        uint2 vv = *(const uint2*)&V[row * HD + c4];
        __half2 v01 = *reinterpret_cast<__half2*>(&vv.x);
        __half2 v23 = *reinterpret_cast<__half2*>(&vv.y);
        Vt[(c4 + 0) * LDV + row] = __low2half(v01);
        Vt[(c4 + 1) * LDV + row] = __high2half(v01);
        Vt[(c4 + 2) * LDV + row] = __low2half(v23);
        Vt[(c4 + 3) * LDV + row] = __high2half(v23);
    }

    int t0r = halfb * 128 + wi * 16;

    uint32_t qa[2][4];
    #pragma unroll
    for (int kt = 0; kt < 2; kt++) {
        qa[kt][0] = *(const uint32_t*)&Q[(size_t)(t0r + g)     * HD + kt * 16 + 2 * c];
        qa[kt][1] = *(const uint32_t*)&Q[(size_t)(t0r + g + 8) * HD + kt * 16 + 2 * c];
        qa[kt][2] = *(const uint32_t*)&Q[(size_t)(t0r + g)     * HD + kt * 16 + 2 * c + 8];
        qa[kt][3] = *(const uint32_t*)&Q[(size_t)(t0r + g + 8) * HD + kt * 16 + 2 * c + 8];
    }

    float o[4][4];
    #pragma unroll
    for (int j = 0; j < 4; j++)
        #pragma unroll
        for (int e = 0; e < 4; e++) o[j][e] = 0.f;
    float lacc[4] = {0.f, 0.f, 0.f, 0.f};
    uint32_t bones = (lane < 4) ? 0x3C003C00u : 0u;

    __syncthreads();

    #pragma unroll 1
    for (int ch = 0; ch < 4; ch++) {
        int n0 = ch * 64;
        float s[8][4];
        #pragma unroll
        for (int nt = 0; nt < 8; nt++)
            #pragma unroll
            for (int e = 0; e < 4; e++) s[nt][e] = 0.f;

        #pragma unroll
        for (int kt = 0; kt < 2; kt++) {
            #pragma unroll
            for (int nt = 0; nt < 8; nt++) {
                const __half* kp = &Ks[(n0 + nt * 8 + g) * LDK + kt * 16 + 2 * c];
                uint32_t b0 = *(const uint32_t*)kp;
                uint32_t b1 = *(const uint32_t*)(kp + 8);
                mma_f16(s[nt], qa[kt][0], qa[kt][1], qa[kt][2], qa[kt][3], b0, b1);
            }
        }
        #pragma unroll
        for (int kt2 = 0; kt2 < 4; kt2++) {
            uint32_t pa0 = ex2h2(packh2(s[2 * kt2][0],     s[2 * kt2][1]));
            uint32_t pa1 = ex2h2(packh2(s[2 * kt2][2],     s[2 * kt2][3]));
            uint32_t pa2 = ex2h2(packh2(s[2 * kt2 + 1][0], s[2 * kt2 + 1][1]));
            uint32_t pa3 = ex2h2(packh2(s[2 * kt2 + 1][2], s[2 * kt2 + 1][3]));
            mma_f16(lacc, pa0, pa1, pa2, pa3, bones, bones);
            #pragma unroll
            for (int j = 0; j < 4; j++) {
                const __half* vp = &Vt[(j * 8 + g) * LDV + n0 + kt2 * 16 + 2 * c];
                uint32_t b0 = *(const uint32_t*)vp;
                uint32_t b1 = *(const uint32_t*)(vp + 8);
                mma_f16(o[j], pa0, pa1, pa2, pa3, b0, b1);
            }
        }
    }

    float l0v = __shfl_sync(0xffffffffu, lacc[0], lane & ~3);
    float l1v = __shfl_sync(0xffffffffu, lacc[2], lane & ~3);
    float inv0 = 1.f / l0v, inv1 = 1.f / l1v;
    __half* Cp = g_ctx_h + (size_t)(bz >> 3) * (T * C) + (bz & 7) * HD;
    #pragma unroll
    for (int j = 0; j < 4; j++) {
        *(uint32_t*)&Cp[(size_t)(t0r + g)     * C + j * 8 + 2 * c] =
            packh2(o[j][0] * inv0, o[j][1] * inv0);
        *(uint32_t*)&Cp[(size_t)(t0r + g + 8) * C + j * 8 + 2 * c] =
            packh2(o[j][2] * inv1, o[j][3] * inv1);
    }
}

// ---------------- launcher ----------------
extern "C" void kernel_launch(void* const* d_in, const int* in_sizes, int n_in,
                              void* d_out, int out_size) {
    const float* x    = (const float*)d_in[0];
    const float* lnw  = (const float*)d_in[1];
    const float* lnb  = (const float*)d_in[2];
    const float* wqkv = (const float*)d_in[3];
    const float* bqkv = (const float*)d_in[4];
    const float* wout = (const float*)d_in[5];
    const float* bout = (const float*)d_in[6];
    float* out = (float*)d_out;

    constexpr int LNQKV_SMEM = 111616;
    constexpr int GEMM_SMEM  = 3 * 2 * 128 * 72 * 2;          // 110592
    constexpr int ATTN2_SMEM = (256 * 40 + 32 * 264) * 2;     // 37376

    static bool attr_done = false;
    if (!attr_done) {
        cudaFuncSetAttribute((const void*)k_lnqkv,
                             cudaFuncAttributeMaxDynamicSharedMemorySize, LNQKV_SMEM);
        cudaFuncSetAttribute((const void*)k_outproj,
                             cudaFuncAttributeMaxDynamicSharedMemorySize, GEMM_SMEM);
        cudaFuncSetAttribute((const void*)k_attn2,
                             cudaFuncAttributeMaxDynamicSharedMemorySize, ATTN2_SMEM);
        attr_done = true;
    }

    k_cvtw<<<768, 256>>>(wqkv, wout);
    k_lnqkv<<<MTOK / 128, 256, LNQKV_SMEM>>>(x, lnw, lnb, bqkv);
    k_attn2<<<NWIN * HEADS * 2, 256, ATTN2_SMEM>>>();
    k_outproj<<<dim3(2, MTOK / 128), 256, GEMM_SMEM>>>(bout, x, out);
}

// round 14
// speedup vs baseline: 1.0728x; 1.0728x over previous
#include <cuda_runtime.h>
#include <cuda_fp16.h>
#include <mma.h>
#include <math.h>
#include <cstdint>

using namespace nvcuda;

static constexpr int BATCH = 8;
static constexpr int C     = 256;
static constexpr int HH    = 128;
static constexpr int WWID  = 128;
static constexpr int NWIN  = 512;
static constexpr int T     = 256;
static constexpr int HEADS = 8;
static constexpr int HD    = 32;
static constexpr int MTOK  = NWIN * T;  // 131072

// ---------------- scratch ----------------
__device__ __align__(16) __half g_xn_h [(size_t)MTOK * C];
__device__ __align__(16) __half g_qh  [(size_t)MTOK * C];   // [win][h][t][e]
__device__ __align__(16) __half g_kh  [(size_t)MTOK * C];
__device__ __align__(16) __half g_vh  [(size_t)MTOK * C];
__device__ __align__(16) __half g_ctx_h[(size_t)MTOK * C];  // [win][t][h*32+e]
__device__ __align__(16) __half g_wqkv_h[768 * 256];
__device__ __align__(16) __half g_wout_h[256 * 256];

__device__ __forceinline__ uint32_t packh2(float lo, float hi) {
    __half2 h = __floats2half2_rn(lo, hi);
    return *reinterpret_cast<uint32_t*>(&h);
}
__device__ __forceinline__ uint32_t ex2h2(uint32_t a) {
    uint32_t d;
    asm("ex2.approx.f16x2 %0, %1;" : "=r"(d) : "r"(a));
    return d;
}
__device__ __forceinline__ uint32_t smem_u32(const void* p) {
    return (uint32_t)__cvta_generic_to_shared(p);
}
__device__ __forceinline__ void cp16(uint32_t dst, const void* src) {
    asm volatile("cp.async.cg.shared.global [%0], [%1], 16;" :: "r"(dst), "l"(src));
}
#define CP_COMMIT() asm volatile("cp.async.commit_group;")
#define CP_WAIT(n)  asm volatile("cp.async.wait_group %0;" :: "n"(n))

__device__ __forceinline__ void mma_f16(float* d,
        uint32_t a0, uint32_t a1, uint32_t a2, uint32_t a3,
        uint32_t b0, uint32_t b1) {
    asm volatile("mma.sync.aligned.m16n8k16.row.col.f32.f16.f16.f32 "
        "{%0,%1,%2,%3}, {%4,%5,%6,%7}, {%8,%9}, {%0,%1,%2,%3};"
        : "+f"(d[0]), "+f"(d[1]), "+f"(d[2]), "+f"(d[3])
        : "r"(a0), "r"(a1), "r"(a2), "r"(a3), "r"(b0), "r"(b1));
}
__device__ __forceinline__ void ldsm_x4(uint32_t* r, uint32_t addr) {
    asm volatile("ldmatrix.sync.aligned.m8n8.x4.shared.b16 {%0,%1,%2,%3}, [%4];"
        : "=r"(r[0]), "=r"(r[1]), "=r"(r[2]), "=r"(r[3]) : "r"(addr));
}

// ---------------- kernel 0: weight conversion ----------------
__global__ void k_cvtw(const float* __restrict__ wqkv, const float* __restrict__ wout) {
    int i = blockIdx.x * 256 + threadIdx.x;
    if (i < 768 * 256) g_wqkv_h[i] = __float2half(wqkv[i]);
    if (i < 256 * 256) g_wout_h[i] = __float2half(wout[i]);
}

// ---------------- kernel 1: fused partition + LN stats + normalize --------
__global__ __launch_bounds__(256) void k_pn(const float* __restrict__ x,
                                            const float* __restrict__ lw,
                                            const float* __restrict__ lb) {
    constexpr int LDX = 258;            // halves per row; 129 words (odd)
    extern __shared__ char smc[];
    __half*  xb  = (__half*)smc;                       // [256][258]
    __half2* xb2 = (__half2*)smc;
    float* smu = (float*)(smc + 256 * LDX * 2);
    float* srs = smu + 256;

    int tid = threadIdx.x;
    int n   = blockIdx.x;
    int b  = n >> 6;
    int wi = (n >> 3) & 7;
    int wj = n & 7;

    #pragma unroll
    for (int chunk = 0; chunk < 8; chunk++) {
        int c0 = chunk * 32;
        #pragma unroll
        for (int r = 0; r < 8; r++) {
            int rowid = r * 64 + (tid >> 2);
            int cl = rowid >> 4, ti = rowid & 15;
            int f4 = tid & 3;
            const float4* gp = (const float4*)(x
                + (size_t)((b * C + c0 + cl) * HH + wi * 16 + ti) * WWID
                + wj * 16) + f4;
            float4 v = *gp;
            int tb = ti * 16 + f4 * 4;
            xb[(tb + 0) * LDX + c0 + cl] = __float2half(v.x);
            xb[(tb + 1) * LDX + c0 + cl] = __float2half(v.y);
            xb[(tb + 2) * LDX + c0 + cl] = __float2half(v.z);
            xb[(tb + 3) * LDX + c0 + cl] = __float2half(v.w);
        }
    }
    __syncthreads();

    {
        int t = tid;
        float s = 0.f, s2 = 0.f;
        #pragma unroll 16
        for (int w = 0; w < 128; w++) {
            float2 f = __half22float2(xb2[t * 129 + w]);
            s += f.x + f.y;
            s2 += f.x * f.x + f.y * f.y;
        }
        float mu  = s * (1.f / C);
        float var = s2 * (1.f / C) - mu * mu;
        smu[t] = mu;
        srs[t] = rsqrtf(var + 1e-5f);
    }
    __syncthreads();

    #pragma unroll
    for (int pp = 0; pp < 8; pp++) {
        int t = pp * 32 + (tid >> 3);
        float mu = smu[t], rs = srs[t];
        #pragma unroll
        for (int i = 0; i < 8; i++) {
            int c = (tid & 7) * 4 + i * 32;
            int wbase = t * 129 + (c >> 1);
            float2 f0 = __half22float2(xb2[wbase]);
            float2 f1 = __half22float2(xb2[wbase + 1]);
            float4 w4 = *(const float4*)&lw[c];
            float4 b4 = *(const float4*)&lb[c];
            float o0 = (f0.x - mu) * rs * w4.x + b4.x;
            float o1 = (f0.y - mu) * rs * w4.y + b4.y;
            float o2 = (f1.x - mu) * rs * w4.z + b4.z;
            float o3 = (f1.y - mu) * rs * w4.w + b4.w;
            *(uint2*)&g_xn_h[((size_t)n * T + t) * C + c] =
                make_uint2(packh2(o0, o1), packh2(o2, o3));
        }
    }
}

// ---------------- kernel 2: QKV GEMM (raw mma + ldsm, register epilogue) --
// A=g_xn_h [M,256] row-major, B=g_wqkv_h [768,256] NK. 3-stage cp.async.
// grid (6, 1024). Warp tile 64x32 (FM=4, NT=4 n8-tiles).
__global__ __launch_bounds__(256, 2) void k_qkv(const float* __restrict__ bias) {
    constexpr int BM = 128, BK = 64, KDIM = 256;
    constexpr int NT = 256;
    constexpr int LDA = BK + 8;   // 72 halves
    constexpr int LDB = BK + 8;
    constexpr int ASTG = BM * LDA;
    constexpr int STG  = 2 * ASTG;
    constexpr int NS   = 3;
    constexpr int KT   = KDIM / BK;  // 4

    extern __shared__ __half smh[];

    int tid = threadIdx.x;
    int lane = tid & 31;
    int wi = tid >> 5;
    int wmi = wi & 1;       // 2 M-warps x 64 rows
    int wni = wi >> 1;      // 4 N-warps x 32 cols
    int m0 = blockIdx.y * BM;
    int n0 = blockIdx.x * 128;
    int g = lane >> 2, c = lane & 3;

    auto stageAB = [&](int kb, int s) {
        __half* As = smh + s * STG;
        __half* Bs = As + ASTG;
        #pragma unroll
        for (int r = 0; r < BM * BK / (NT * 8); r++) {
            int i = (r * NT + tid) * 8;
            int m = i / BK, k = i % BK;
            cp16(smem_u32(&As[m * LDA + k]), &g_xn_h[(size_t)(m0 + m) * KDIM + kb + k]);
        }
        #pragma unroll
        for (int r = 0; r < 128 * BK / (NT * 8); r++) {
            int i = (r * NT + tid) * 8;
            int n = i / BK, k = i % BK;
            cp16(smem_u32(&Bs[n * LDB + k]), &g_wqkv_h[(size_t)(n0 + n) * KDIM + kb + k]);
        }
    };

    float cf[4][4][4];
    #pragma unroll
    for (int fm = 0; fm < 4; fm++)
        #pragma unroll
        for (int nt = 0; nt < 4; nt++)
            #pragma unroll
            for (int e = 0; e < 4; e++) cf[fm][nt][e] = 0.f;

    stageAB(0, 0); CP_COMMIT();
    stageAB(BK, 1); CP_COMMIT();
    CP_WAIT(1);
    __syncthreads();

    // fragment lane geometry
    int a_row = wmi * 64 + (lane & 15);          // + fm*16
    int a_col = ((lane >> 4) & 1) * 8;           // + kk*16
    int b_row = wni * 32 + ((lane >> 4) & 1) * 8 + (lane & 7);  // + bp*16
    int b_col = ((lane >> 3) & 1) * 8;           // + kk*16

    #pragma unroll
    for (int kbi = 0; kbi < KT; kbi++) {
        __half* As = smh + (kbi % NS) * STG;
        __half* Bs = As + ASTG;
        uint32_t a_base = smem_u32(As);
        uint32_t b_base = smem_u32(Bs);
        #pragma unroll
        for (int kk = 0; kk < 4; kk++) {
            uint32_t af[4][4];
            #pragma unroll
            for (int fm = 0; fm < 4; fm++)
                ldsm_x4(af[fm], a_base + 2 * ((a_row + fm * 16) * LDA + kk * 16 + a_col));
            uint32_t bf[4][2];
            #pragma unroll
            for (int bp = 0; bp < 2; bp++) {
                uint32_t tmp[4];
                ldsm_x4(tmp, b_base + 2 * ((b_row + bp * 16) * LDB + kk * 16 + b_col));
                bf[bp * 2][0] = tmp[0]; bf[bp * 2][1] = tmp[1];
                bf[bp * 2 + 1][0] = tmp[2]; bf[bp * 2 + 1][1] = tmp[3];
            }
            #pragma unroll
            for (int fm = 0; fm < 4; fm++)
                #pragma unroll
                for (int nt = 0; nt < 4; nt++)
                    mma_f16(cf[fm][nt], af[fm][0], af[fm][1], af[fm][2], af[fm][3],
                            bf[nt][0], bf[nt][1]);
        }
        if (kbi + NS - 1 < KT) {
            stageAB((kbi + NS - 1) * BK, (kbi + NS - 1) % NS);
            CP_COMMIT();
            CP_WAIT(1);
        } else {
            CP_WAIT(0);
        }
        __syncthreads();
    }

    // ---- register epilogue: scatter q/k/v (layout proven in R13) ----
    #pragma unroll
    for (int nt = 0; nt < 4; nt++) {
        int col = n0 + wni * 32 + nt * 8 + 2 * c;
        float2 bb = *(const float2*)&bias[col];
        int part = col >> 8;
        int d = col & 255;
        int hh = d >> 5, e = d & 31;
        float scale = (part == 0) ? 0.25505697382625574f : 1.f;  // 1/sqrt(32)*log2e
        __half* dst = (part == 0) ? g_qh : (part == 1) ? g_kh : g_vh;
        #pragma unroll
        for (int fm = 0; fm < 4; fm++) {
            int r0 = m0 + wmi * 64 + fm * 16 + g;
            float v00 = (cf[fm][nt][0] + bb.x) * scale;
            float v01 = (cf[fm][nt][1] + bb.y) * scale;
            float v10 = (cf[fm][nt][2] + bb.x) * scale;
            float v11 = (cf[fm][nt][3] + bb.y) * scale;
            size_t o0 = ((size_t)((r0 >> 8) * HEADS + hh) * T + (r0 & 255)) * HD + e;
            size_t o1 = o0 + 8 * (size_t)HD;
            *(uint32_t*)&dst[o0] = packh2(v00, v01);
            *(uint32_t*)&dst[o1] = packh2(v10, v11);
        }
    }
}

// ---------------- kernel 3: out projection (wmma + L2 prefetch of x) ------
__global__ __launch_bounds__(256, 2) void k_outproj(const float* __restrict__ bias,
                                                    const float* __restrict__ x,
                                                    float* __restrict__ out) {
    constexpr int BM = 128, BN = 128, BK = 64, WM = 64, WN = 32, KDIM = 256;
    constexpr int WARPS_M = BM / WM;
    constexpr int NT = 256;
    constexpr int LDA = BK + 8;
    constexpr int LDB = BK + 8;
    constexpr int FM = WM / 16, FN = WN / 16;
    constexpr int ASTG = BM * LDA;
    constexpr int STG  = 2 * ASTG;
    constexpr int NS   = 3;
    constexpr int KT   = KDIM / BK;

    extern __shared__ float smf[];
    __half* smh = (__half*)smf;

    int tid = threadIdx.x;
    int m0 = blockIdx.y * BM;
    int n0 = blockIdx.x * BN;
    int wi = tid >> 5;
    int wmi = wi % WARPS_M;
    int wni = wi / WARPS_M;

    int n_win = m0 >> 8;
    int halfb = (m0 >> 7) & 1;
    int b  = n_win >> 6;
    int wr = (n_win >> 3) & 7;
    int wc = n_win & 7;

    wmma::fragment<wmma::accumulator, 16, 16, 16, float> cf[FM][FN];
    #pragma unroll
    for (int fm = 0; fm < FM; fm++)
        #pragma unroll
        for (int fn = 0; fn < FN; fn++)
            wmma::fill_fragment(cf[fm][fn], 0.f);

    auto stageAB = [&](int kb, int s) {
        __half* As = smh + s * STG;
        __half* Bs = As + ASTG;
        #pragma unroll
        for (int r = 0; r < BM * BK / (NT * 8); r++) {
            int i = (r * NT + tid) * 8;
            int m = i / BK, k = i % BK;
            cp16(smem_u32(&As[m * LDA + k]), &g_ctx_h[(size_t)(m0 + m) * KDIM + kb + k]);
        }
        #pragma unroll
        for (int r = 0; r < BN * BK / (NT * 8); r++) {
            int i = (r * NT + tid) * 8;
            int n = i / BK, k = i % BK;
            cp16(smem_u32(&Bs[n * LDB + k]), &g_wout_h[(size_t)(n0 + n) * KDIM + kb + k]);
        }
    };

    stageAB(0, 0); CP_COMMIT();
    stageAB(BK, 1); CP_COMMIT();

    // prefetch the residual x tile into L2 while GEMM runs
    #pragma unroll
    for (int r = 0; r < 4; r++) {
        int idx = r * 256 + tid;
        int cl = idx >> 3, ti = idx & 7;
        const float* pa = x + ((size_t)(b * C + n0 + cl) * HH + wr * 16 + halfb * 8 + ti) * WWID
                        + wc * 16;
        asm volatile("prefetch.global.L2 [%0];" :: "l"(pa));
    }

    CP_WAIT(1);
    __syncthreads();

    #pragma unroll
    for (int kbi = 0; kbi < KT; kbi++) {
        __half* As = smh + (kbi % NS) * STG;
        __half* Bs = As + ASTG;
        #pragma unroll
        for (int kk = 0; kk < BK; kk += 16) {
            wmma::fragment<wmma::matrix_a, 16, 16, 16, __half, wmma::row_major> af[FM];
            #pragma unroll
            for (int fm = 0; fm < FM; fm++)
                wmma::load_matrix_sync(af[fm], &As[(wmi * WM + fm * 16) * LDA + kk], LDA);
            #pragma unroll
            for (int fn = 0; fn < FN; fn++) {
                wmma::fragment<wmma::matrix_b, 16, 16, 16, __half, wmma::col_major> bf;
                wmma::load_matrix_sync(bf, &Bs[(wni * WN + fn * 16) * LDB + kk], LDB);
                #pragma unroll
                for (int fm = 0; fm < FM; fm++)
                    wmma::mma_sync(cf[fm][fn], af[fm], bf, cf[fm][fn]);
            }
        }
        if (kbi + NS - 1 < KT) {
            stageAB((kbi + NS - 1) * BK, (kbi + NS - 1) % NS);
            CP_COMMIT();
            CP_WAIT(1);
        } else {
            CP_WAIT(0);
        }
        __syncthreads();
    }

    // fused bias + residual + window reverse; Cs col-major [channel][token]
    constexpr int LDCT = BM + 4;
    float* Cs = smf;
    #pragma unroll
    for (int fm = 0; fm < FM; fm++)
        #pragma unroll
        for (int fn = 0; fn < FN; fn++)
            wmma::store_matrix_sync(&Cs[(wni * WN + fn * 16) * LDCT + wmi * WM + fm * 16],
                                    cf[fm][fn], LDCT, wmma::mem_col_major);
    __syncthreads();
    #pragma unroll
    for (int r = 0; r < BM * BN / (NT * 4); r++) {
        int idx = r * NT + tid;
        int f4 = idx & 3;
        int ti = (idx >> 2) & 7;
        int cl = idx >> 5;
        int gn = n0 + cl;
        int tok = ti * 16 + f4 * 4;
        float4 v = *(float4*)&Cs[cl * LDCT + tok];
        float bb = bias[gn];
        size_t off = ((size_t)(b * C + gn) * HH + wr * 16 + halfb * 8 + ti) * WWID
                   + wc * 16 + f4 * 4;
        float4 xr = *(const float4*)&x[off];
        float4 o_;
        o_.x = xr.x + v.x + bb;
        o_.y = xr.y + v.y + bb;
        o_.z = xr.z + v.z + bb;
        o_.w = xr.w + v.w + bb;
        *(float4*)&out[off] = o_;
    }
}

// ---------------- fused flash attention (f16x2 exp, l via ones-MMA) -------
__global__ __launch_bounds__(256, 2) void k_attn2() {
    constexpr int LDK = 40;    // halves
    constexpr int LDV = 264;   // halves
    extern __shared__ __half smh[];
    __half* Ks = smh;                 // 256*40
    __half* Vt = smh + 256 * LDK;     // 32*264

    int bz   = blockIdx.x >> 1;
    int halfb = blockIdx.x & 1;
    const __half* Q = g_qh + (size_t)bz * T * HD;
    const __half* K = g_kh + (size_t)bz * T * HD;
    const __half* V = g_vh + (size_t)bz * T * HD;
    int tid = threadIdx.x, wi = tid >> 5, lane = tid & 31;
    int g = lane >> 2, c = lane & 3;

    #pragma unroll
    for (int it = 0; it < 8; it++) {
        int i = it * 256 + tid;
        int row = i >> 3, c4 = (i & 7) * 4;
        *(uint2*)&Ks[row * LDK + c4] = *(const uint2*)&K[row * HD + c4];
        uint2 vv = *(const uint2*)&V[row * HD + c4];
        __half2 v01 = *reinterpret_cast<__half2*>(&vv.x);
        __half2 v23 = *reinterpret_cast<__half2*>(&vv.y);
        Vt[(c4 + 0) * LDV + row] = __low2half(v01);
        Vt[(c4 + 1) * LDV + row] = __high2half(v01);
        Vt[(c4 + 2) * LDV + row] = __low2half(v23);
        Vt[(c4 + 3) * LDV + row] = __high2half(v23);
    }

    int t0r = halfb * 128 + wi * 16;

    uint32_t qa[2][4];
    #pragma unroll
    for (int kt = 0; kt < 2; kt++) {
        qa[kt][0] = *(const uint32_t*)&Q[(size_t)(t0r + g)     * HD + kt * 16 + 2 * c];
        qa[kt][1] = *(const uint32_t*)&Q[(size_t)(t0r + g + 8) * HD + kt * 16 + 2 * c];
        qa[kt][2] = *(const uint32_t*)&Q[(size_t)(t0r + g)     * HD + kt * 16 + 2 * c + 8];
        qa[kt][3] = *(const uint32_t*)&Q[(size_t)(t0r + g + 8) * HD + kt * 16 + 2 * c + 8];
    }

    float o[4][4];
    #pragma unroll
    for (int j = 0; j < 4; j++)
        #pragma unroll
        for (int e = 0; e < 4; e++) o[j][e] = 0.f;
    float lacc[4] = {0.f, 0.f, 0.f, 0.f};
    uint32_t bones = (lane < 4) ? 0x3C003C00u : 0u;

    __syncthreads();

    #pragma unroll 1
    for (int ch = 0; ch < 4; ch++) {
        int n0 = ch * 64;
        float s[8][4];
        #pragma unroll
        for (int nt = 0; nt < 8; nt++)
            #pragma unroll
            for (int e = 0; e < 4; e++) s[nt][e] = 0.f;

        #pragma unroll
        for (int kt = 0; kt < 2; kt++) {
            #pragma unroll
            for (int nt = 0; nt < 8; nt++) {
                const __half* kp = &Ks[(n0 + nt * 8 + g) * LDK + kt * 16 + 2 * c];
                uint32_t b0 = *(const uint32_t*)kp;
                uint32_t b1 = *(const uint32_t*)(kp + 8);
                mma_f16(s[nt], qa[kt][0], qa[kt][1], qa[kt][2], qa[kt][3], b0, b1);
            }
        }
        #pragma unroll
        for (int kt2 = 0; kt2 < 4; kt2++) {
            uint32_t pa0 = ex2h2(packh2(s[2 * kt2][0],     s[2 * kt2][1]));
            uint32_t pa1 = ex2h2(packh2(s[2 * kt2][2],     s[2 * kt2][3]));
            uint32_t pa2 = ex2h2(packh2(s[2 * kt2 + 1][0], s[2 * kt2 + 1][1]));
            uint32_t pa3 = ex2h2(packh2(s[2 * kt2 + 1][2], s[2 * kt2 + 1][3]));
            mma_f16(lacc, pa0, pa1, pa2, pa3, bones, bones);
            #pragma unroll
            for (int j = 0; j < 4; j++) {
                const __half* vp = &Vt[(j * 8 + g) * LDV + n0 + kt2 * 16 + 2 * c];
                uint32_t b0 = *(const uint32_t*)vp;
                uint32_t b1 = *(const uint32_t*)(vp + 8);
                mma_f16(o[j], pa0, pa1, pa2, pa3, b0, b1);
            }
        }
    }

    float l0v = __shfl_sync(0xffffffffu, lacc[0], lane & ~3);
    float l1v = __shfl_sync(0xffffffffu, lacc[2], lane & ~3);
    float inv0 = 1.f / l0v, inv1 = 1.f / l1v;
    __half* Cp = g_ctx_h + (size_t)(bz >> 3) * (T * C) + (bz & 7) * HD;
    #pragma unroll
    for (int j = 0; j < 4; j++) {
        *(uint32_t*)&Cp[(size_t)(t0r + g)     * C + j * 8 + 2 * c] =
            packh2(o[j][0] * inv0, o[j][1] * inv0);
        *(uint32_t*)&Cp[(size_t)(t0r + g + 8) * C + j * 8 + 2 * c] =
            packh2(o[j][2] * inv1, o[j][3] * inv1);
    }
}

// ---------------- launcher ----------------
extern "C" void kernel_launch(void* const* d_in, const int* in_sizes, int n_in,
                              void* d_out, int out_size) {
    const float* x    = (const float*)d_in[0];
    const float* lnw  = (const float*)d_in[1];
    const float* lnb  = (const float*)d_in[2];
    const float* wqkv = (const float*)d_in[3];
    const float* bqkv = (const float*)d_in[4];
    const float* wout = (const float*)d_in[5];
    const float* bout = (const float*)d_in[6];
    float* out = (float*)d_out;

    constexpr int GEMM_SMEM  = 3 * 2 * 128 * 72 * 2;          // 110592
    constexpr int ATTN2_SMEM = (256 * 40 + 32 * 264) * 2;     // 37376
    constexpr int PN_SMEM    = 256 * 258 * 2 + 512 * 4;       // 134144

    static bool attr_done = false;
    if (!attr_done) {
        cudaFuncSetAttribute((const void*)k_qkv,
                             cudaFuncAttributeMaxDynamicSharedMemorySize, GEMM_SMEM);
        cudaFuncSetAttribute((const void*)k_outproj,
                             cudaFuncAttributeMaxDynamicSharedMemorySize, GEMM_SMEM);
        cudaFuncSetAttribute((const void*)k_attn2,
                             cudaFuncAttributeMaxDynamicSharedMemorySize, ATTN2_SMEM);
        cudaFuncSetAttribute((const void*)k_pn,
                             cudaFuncAttributeMaxDynamicSharedMemorySize, PN_SMEM);
        attr_done = true;
    }

    k_cvtw<<<768, 256>>>(wqkv, wout);
    k_pn<<<NWIN, 256, PN_SMEM>>>(x, lnw, lnb);
    k_qkv<<<dim3(6, MTOK / 128), 256, GEMM_SMEM>>>(bqkv);
    k_attn2<<<NWIN * HEADS * 2, 256, ATTN2_SMEM>>>();
    k_outproj<<<dim3(2, MTOK / 128), 256, GEMM_SMEM>>>(bout, x, out);
}

// round 15
// speedup vs baseline: 1.1463x; 1.0686x over previous
#include <cuda_runtime.h>
#include <cuda_fp16.h>
#include <mma.h>
#include <math.h>
#include <cstdint>

using namespace nvcuda;

static constexpr int BATCH = 8;
static constexpr int C     = 256;
static constexpr int HH    = 128;
static constexpr int WWID  = 128;
static constexpr int NWIN  = 512;
static constexpr int T     = 256;
static constexpr int HEADS = 8;
static constexpr int HD    = 32;
static constexpr int MTOK  = NWIN * T;  // 131072

// ---------------- scratch ----------------
__device__ __align__(16) __half g_xn_h [(size_t)MTOK * C];
__device__ __align__(16) __half g_qh  [(size_t)MTOK * C];   // [win][h][t][e]
__device__ __align__(16) __half g_kh  [(size_t)MTOK * C];
__device__ __align__(16) __half g_vh  [(size_t)MTOK * C];
__device__ __align__(16) __half g_ctx_h[(size_t)MTOK * C];  // [win][t][h*32+e]
__device__ __align__(16) __half g_wqkv_h[768 * 256];
__device__ __align__(16) __half g_wout_h[256 * 256];

__device__ __forceinline__ uint32_t packh2(float lo, float hi) {
    __half2 h = __floats2half2_rn(lo, hi);
    return *reinterpret_cast<uint32_t*>(&h);
}
__device__ __forceinline__ uint32_t ex2h2(uint32_t a) {
    uint32_t d;
    asm("ex2.approx.f16x2 %0, %1;" : "=r"(d) : "r"(a));
    return d;
}
__device__ __forceinline__ uint32_t smem_u32(const void* p) {
    return (uint32_t)__cvta_generic_to_shared(p);
}
__device__ __forceinline__ void cp16(uint32_t dst, const void* src) {
    asm volatile("cp.async.cg.shared.global [%0], [%1], 16;" :: "r"(dst), "l"(src));
}
#define CP_COMMIT() asm volatile("cp.async.commit_group;")
#define CP_WAIT(n)  asm volatile("cp.async.wait_group %0;" :: "n"(n))

__device__ __forceinline__ void mma_f16(float* d,
        uint32_t a0, uint32_t a1, uint32_t a2, uint32_t a3,
        uint32_t b0, uint32_t b1) {
    asm volatile("mma.sync.aligned.m16n8k16.row.col.f32.f16.f16.f32 "
        "{%0,%1,%2,%3}, {%4,%5,%6,%7}, {%8,%9}, {%0,%1,%2,%3};"
        : "+f"(d[0]), "+f"(d[1]), "+f"(d[2]), "+f"(d[3])
        : "r"(a0), "r"(a1), "r"(a2), "r"(a3), "r"(b0), "r"(b1));
}
__device__ __forceinline__ void ldsm_x4(uint32_t* r, uint32_t addr) {
    asm volatile("ldmatrix.sync.aligned.m8n8.x4.shared.b16 {%0,%1,%2,%3}, [%4];"
        : "=r"(r[0]), "=r"(r[1]), "=r"(r[2]), "=r"(r[3]) : "r"(addr));
}

// ---------------- kernel 0: weight conversion ----------------
__global__ void k_cvtw(const float* __restrict__ wqkv, const float* __restrict__ wout) {
    int i = blockIdx.x * 256 + threadIdx.x;
    if (i < 768 * 256) g_wqkv_h[i] = __float2half(wqkv[i]);
    if (i < 256 * 256) g_wout_h[i] = __float2half(wout[i]);
}

// ---------------- kernel 1: fused partition + LN stats + normalize --------
__global__ __launch_bounds__(256) void k_pn(const float* __restrict__ x,
                                            const float* __restrict__ lw,
                                            const float* __restrict__ lb) {
    constexpr int LDX = 258;            // halves per row; 129 words (odd)
    extern __shared__ char smc[];
    __half*  xb  = (__half*)smc;                       // [256][258]
    __half2* xb2 = (__half2*)smc;
    float* smu = (float*)(smc + 256 * LDX * 2);
    float* srs = smu + 256;

    int tid = threadIdx.x;
    int n   = blockIdx.x;
    int b  = n >> 6;
    int wi = (n >> 3) & 7;
    int wj = n & 7;

    #pragma unroll
    for (int chunk = 0; chunk < 8; chunk++) {
        int c0 = chunk * 32;
        #pragma unroll
        for (int r = 0; r < 8; r++) {
            int rowid = r * 64 + (tid >> 2);
            int cl = rowid >> 4, ti = rowid & 15;
            int f4 = tid & 3;
            const float4* gp = (const float4*)(x
                + (size_t)((b * C + c0 + cl) * HH + wi * 16 + ti) * WWID
                + wj * 16) + f4;
            float4 v = *gp;
            int tb = ti * 16 + f4 * 4;
            xb[(tb + 0) * LDX + c0 + cl] = __float2half(v.x);
            xb[(tb + 1) * LDX + c0 + cl] = __float2half(v.y);
            xb[(tb + 2) * LDX + c0 + cl] = __float2half(v.z);
            xb[(tb + 3) * LDX + c0 + cl] = __float2half(v.w);
        }
    }
    __syncthreads();

    {
        int t = tid;
        float s = 0.f, s2 = 0.f;
        #pragma unroll 16
        for (int w = 0; w < 128; w++) {
            float2 f = __half22float2(xb2[t * 129 + w]);
            s += f.x + f.y;
            s2 += f.x * f.x + f.y * f.y;
        }
        float mu  = s * (1.f / C);
        float var = s2 * (1.f / C) - mu * mu;
        smu[t] = mu;
        srs[t] = rsqrtf(var + 1e-5f);
    }
    __syncthreads();

    #pragma unroll
    for (int pp = 0; pp < 8; pp++) {
        int t = pp * 32 + (tid >> 3);
        float mu = smu[t], rs = srs[t];
        #pragma unroll
        for (int i = 0; i < 8; i++) {
            int c = (tid & 7) * 4 + i * 32;
            int wbase = t * 129 + (c >> 1);
            float2 f0 = __half22float2(xb2[wbase]);
            float2 f1 = __half22float2(xb2[wbase + 1]);
            float4 w4 = *(const float4*)&lw[c];
            float4 b4 = *(const float4*)&lb[c];
            float o0 = (f0.x - mu) * rs * w4.x + b4.x;
            float o1 = (f0.y - mu) * rs * w4.y + b4.y;
            float o2 = (f1.x - mu) * rs * w4.z + b4.z;
            float o3 = (f1.y - mu) * rs * w4.w + b4.w;
            *(uint2*)&g_xn_h[((size_t)n * T + t) * C + c] =
                make_uint2(packh2(o0, o1), packh2(o2, o3));
        }
    }
}

// ---------------- kernel 2: QKV GEMM (raw mma + ldsm, register epilogue) --
__global__ __launch_bounds__(256, 2) void k_qkv(const float* __restrict__ bias) {
    constexpr int BM = 128, BK = 64, KDIM = 256;
    constexpr int NT = 256;
    constexpr int LDA = BK + 8;   // 72 halves
    constexpr int LDB = BK + 8;
    constexpr int ASTG = BM * LDA;
    constexpr int STG  = 2 * ASTG;
    constexpr int NS   = 3;
    constexpr int KT   = KDIM / BK;  // 4

    extern __shared__ __half smh[];

    int tid = threadIdx.x;
    int lane = tid & 31;
    int wi = tid >> 5;
    int wmi = wi & 1;       // 2 M-warps x 64 rows
    int wni = wi >> 1;      // 4 N-warps x 32 cols
    int m0 = blockIdx.y * BM;
    int n0 = blockIdx.x * 128;
    int g = lane >> 2, c = lane & 3;

    auto stageAB = [&](int kb, int s) {
        __half* As = smh + s * STG;
        __half* Bs = As + ASTG;
        #pragma unroll
        for (int r = 0; r < BM * BK / (NT * 8); r++) {
            int i = (r * NT + tid) * 8;
            int m = i / BK, k = i % BK;
            cp16(smem_u32(&As[m * LDA + k]), &g_xn_h[(size_t)(m0 + m) * KDIM + kb + k]);
        }
        #pragma unroll
        for (int r = 0; r < 128 * BK / (NT * 8); r++) {
            int i = (r * NT + tid) * 8;
            int n = i / BK, k = i % BK;
            cp16(smem_u32(&Bs[n * LDB + k]), &g_wqkv_h[(size_t)(n0 + n) * KDIM + kb + k]);
        }
    };

    float cf[4][4][4];
    #pragma unroll
    for (int fm = 0; fm < 4; fm++)
        #pragma unroll
        for (int nt = 0; nt < 4; nt++)
            #pragma unroll
            for (int e = 0; e < 4; e++) cf[fm][nt][e] = 0.f;

    stageAB(0, 0); CP_COMMIT();
    stageAB(BK, 1); CP_COMMIT();
    CP_WAIT(1);
    __syncthreads();

    int a_row = wmi * 64 + (lane & 15);
    int a_col = ((lane >> 4) & 1) * 8;
    int b_row = wni * 32 + ((lane >> 4) & 1) * 8 + (lane & 7);
    int b_col = ((lane >> 3) & 1) * 8;

    #pragma unroll
    for (int kbi = 0; kbi < KT; kbi++) {
        __half* As = smh + (kbi % NS) * STG;
        __half* Bs = As + ASTG;
        uint32_t a_base = smem_u32(As);
        uint32_t b_base = smem_u32(Bs);
        #pragma unroll
        for (int kk = 0; kk < 4; kk++) {
            uint32_t af[4][4];
            #pragma unroll
            for (int fm = 0; fm < 4; fm++)
                ldsm_x4(af[fm], a_base + 2 * ((a_row + fm * 16) * LDA + kk * 16 + a_col));
            uint32_t bf[4][2];
            #pragma unroll
            for (int bp = 0; bp < 2; bp++) {
                uint32_t tmp[4];
                ldsm_x4(tmp, b_base + 2 * ((b_row + bp * 16) * LDB + kk * 16 + b_col));
                bf[bp * 2][0] = tmp[0]; bf[bp * 2][1] = tmp[1];
                bf[bp * 2 + 1][0] = tmp[2]; bf[bp * 2 + 1][1] = tmp[3];
            }
            #pragma unroll
            for (int fm = 0; fm < 4; fm++)
                #pragma unroll
                for (int nt = 0; nt < 4; nt++)
                    mma_f16(cf[fm][nt], af[fm][0], af[fm][1], af[fm][2], af[fm][3],
                            bf[nt][0], bf[nt][1]);
        }
        if (kbi + NS - 1 < KT) {
            stageAB((kbi + NS - 1) * BK, (kbi + NS - 1) % NS);
            CP_COMMIT();
            CP_WAIT(1);
        } else {
            CP_WAIT(0);
        }
        __syncthreads();
    }

    #pragma unroll
    for (int nt = 0; nt < 4; nt++) {
        int col = n0 + wni * 32 + nt * 8 + 2 * c;
        float2 bb = *(const float2*)&bias[col];
        int part = col >> 8;
        int d = col & 255;
        int hh = d >> 5, e = d & 31;
        float scale = (part == 0) ? 0.25505697382625574f : 1.f;  // 1/sqrt(32)*log2e
        __half* dst = (part == 0) ? g_qh : (part == 1) ? g_kh : g_vh;
        #pragma unroll
        for (int fm = 0; fm < 4; fm++) {
            int r0 = m0 + wmi * 64 + fm * 16 + g;
            float v00 = (cf[fm][nt][0] + bb.x) * scale;
            float v01 = (cf[fm][nt][1] + bb.y) * scale;
            float v10 = (cf[fm][nt][2] + bb.x) * scale;
            float v11 = (cf[fm][nt][3] + bb.y) * scale;
            size_t o0 = ((size_t)((r0 >> 8) * HEADS + hh) * T + (r0 & 255)) * HD + e;
            size_t o1 = o0 + 8 * (size_t)HD;
            *(uint32_t*)&dst[o0] = packh2(v00, v01);
            *(uint32_t*)&dst[o1] = packh2(v10, v11);
        }
    }
}

// ---------------- kernel 3: out projection (wmma + L2 prefetch of x) ------
__global__ __launch_bounds__(256, 2) void k_outproj(const float* __restrict__ bias,
                                                    const float* __restrict__ x,
                                                    float* __restrict__ out) {
    constexpr int BM = 128, BN = 128, BK = 64, WM = 64, WN = 32, KDIM = 256;
    constexpr int WARPS_M = BM / WM;
    constexpr int NT = 256;
    constexpr int LDA = BK + 8;
    constexpr int LDB = BK + 8;
    constexpr int FM = WM / 16, FN = WN / 16;
    constexpr int ASTG = BM * LDA;
    constexpr int STG  = 2 * ASTG;
    constexpr int NS   = 3;
    constexpr int KT   = KDIM / BK;

    extern __shared__ float smf[];
    __half* smh = (__half*)smf;

    int tid = threadIdx.x;
    int m0 = blockIdx.y * BM;
    int n0 = blockIdx.x * BN;
    int wi = tid >> 5;
    int wmi = wi % WARPS_M;
    int wni = wi / WARPS_M;

    int n_win = m0 >> 8;
    int halfb = (m0 >> 7) & 1;
    int b  = n_win >> 6;
    int wr = (n_win >> 3) & 7;
    int wc = n_win & 7;

    wmma::fragment<wmma::accumulator, 16, 16, 16, float> cf[FM][FN];
    #pragma unroll
    for (int fm = 0; fm < FM; fm++)
        #pragma unroll
        for (int fn = 0; fn < FN; fn++)
            wmma::fill_fragment(cf[fm][fn], 0.f);

    auto stageAB = [&](int kb, int s) {
        __half* As = smh + s * STG;
        __half* Bs = As + ASTG;
        #pragma unroll
        for (int r = 0; r < BM * BK / (NT * 8); r++) {
            int i = (r * NT + tid) * 8;
            int m = i / BK, k = i % BK;
            cp16(smem_u32(&As[m * LDA + k]), &g_ctx_h[(size_t)(m0 + m) * KDIM + kb + k]);
        }
        #pragma unroll
        for (int r = 0; r < BN * BK / (NT * 8); r++) {
            int i = (r * NT + tid) * 8;
            int n = i / BK, k = i % BK;
            cp16(smem_u32(&Bs[n * LDB + k]), &g_wout_h[(size_t)(n0 + n) * KDIM + kb + k]);
        }
    };

    stageAB(0, 0); CP_COMMIT();
    stageAB(BK, 1); CP_COMMIT();

    // prefetch the residual x tile into L2 while GEMM runs
    #pragma unroll
    for (int r = 0; r < 4; r++) {
        int idx = r * 256 + tid;
        int cl = idx >> 3, ti = idx & 7;
        const float* pa = x + ((size_t)(b * C + n0 + cl) * HH + wr * 16 + halfb * 8 + ti) * WWID
                        + wc * 16;
        asm volatile("prefetch.global.L2 [%0];" :: "l"(pa));
    }

    CP_WAIT(1);
    __syncthreads();

    #pragma unroll
    for (int kbi = 0; kbi < KT; kbi++) {
        __half* As = smh + (kbi % NS) * STG;
        __half* Bs = As + ASTG;
        #pragma unroll
        for (int kk = 0; kk < BK; kk += 16) {
            wmma::fragment<wmma::matrix_a, 16, 16, 16, __half, wmma::row_major> af[FM];
            #pragma unroll
            for (int fm = 0; fm < FM; fm++)
                wmma::load_matrix_sync(af[fm], &As[(wmi * WM + fm * 16) * LDA + kk], LDA);
            #pragma unroll
            for (int fn = 0; fn < FN; fn++) {
                wmma::fragment<wmma::matrix_b, 16, 16, 16, __half, wmma::col_major> bf;
                wmma::load_matrix_sync(bf, &Bs[(wni * WN + fn * 16) * LDB + kk], LDB);
                #pragma unroll
                for (int fm = 0; fm < FM; fm++)
                    wmma::mma_sync(cf[fm][fn], af[fm], bf, cf[fm][fn]);
            }
        }
        if (kbi + NS - 1 < KT) {
            stageAB((kbi + NS - 1) * BK, (kbi + NS - 1) % NS);
            CP_COMMIT();
            CP_WAIT(1);
        } else {
            CP_WAIT(0);
        }
        __syncthreads();
    }

    constexpr int LDCT = BM + 4;
    float* Cs = smf;
    #pragma unroll
    for (int fm = 0; fm < FM; fm++)
        #pragma unroll
        for (int fn = 0; fn < FN; fn++)
            wmma::store_matrix_sync(&Cs[(wni * WN + fn * 16) * LDCT + wmi * WM + fm * 16],
                                    cf[fm][fn], LDCT, wmma::mem_col_major);
    __syncthreads();
    #pragma unroll
    for (int r = 0; r < BM * BN / (NT * 4); r++) {
        int idx = r * NT + tid;
        int f4 = idx & 3;
        int ti = (idx >> 2) & 7;
        int cl = idx >> 5;
        int gn = n0 + cl;
        int tok = ti * 16 + f4 * 4;
        float4 v = *(float4*)&Cs[cl * LDCT + tok];
        float bb = bias[gn];
        size_t off = ((size_t)(b * C + gn) * HH + wr * 16 + halfb * 8 + ti) * WWID
                   + wc * 16 + f4 * 4;
        float4 xr = *(const float4*)&x[off];
        float4 o_;
        o_.x = xr.x + v.x + bb;
        o_.y = xr.y + v.y + bb;
        o_.z = xr.z + v.z + bb;
        o_.w = xr.w + v.w + bb;
        *(float4*)&out[off] = o_;
    }
}

// ---------------- fused flash attention v3: 32 rows/warp, shared K/V frags
// One CTA per (win,head); each K/V fragment load feeds two m-tiles.
__global__ __launch_bounds__(256, 2) void k_attn3() {
    constexpr int LDK = 40;    // halves
    constexpr int LDV = 264;   // halves
    extern __shared__ __half smh[];
    __half* Ks = smh;                 // 256*40
    __half* Vt = smh + 256 * LDK;     // 32*264

    int bz = blockIdx.x;
    const __half* Q = g_qh + (size_t)bz * T * HD;
    const __half* K = g_kh + (size_t)bz * T * HD;
    const __half* V = g_vh + (size_t)bz * T * HD;
    int tid = threadIdx.x, wi = tid >> 5, lane = tid & 31;
    int g = lane >> 2, c = lane & 3;

    #pragma unroll
    for (int it = 0; it < 8; it++) {
        int i = it * 256 + tid;
        int row = i >> 3, c4 = (i & 7) * 4;
        *(uint2*)&Ks[row * LDK + c4] = *(const uint2*)&K[row * HD + c4];
        uint2 vv = *(const uint2*)&V[row * HD + c4];
        __half2 v01 = *reinterpret_cast<__half2*>(&vv.x);
        __half2 v23 = *reinterpret_cast<__half2*>(&vv.y);
        Vt[(c4 + 0) * LDV + row] = __low2half(v01);
        Vt[(c4 + 1) * LDV + row] = __high2half(v01);
        Vt[(c4 + 2) * LDV + row] = __low2half(v23);
        Vt[(c4 + 3) * LDV + row] = __high2half(v23);
    }

    int t0r = wi * 32;    // warp's first q row (32 rows per warp)

    uint32_t qa[2][2][4];
    #pragma unroll
    for (int fm = 0; fm < 2; fm++)
        #pragma unroll
        for (int kt = 0; kt < 2; kt++) {
            int r0 = t0r + fm * 16 + g;
            qa[fm][kt][0] = *(const uint32_t*)&Q[(size_t)r0       * HD + kt * 16 + 2 * c];
            qa[fm][kt][1] = *(const uint32_t*)&Q[(size_t)(r0 + 8) * HD + kt * 16 + 2 * c];
            qa[fm][kt][2] = *(const uint32_t*)&Q[(size_t)r0       * HD + kt * 16 + 2 * c + 8];
            qa[fm][kt][3] = *(const uint32_t*)&Q[(size_t)(r0 + 8) * HD + kt * 16 + 2 * c + 8];
        }

    float o[2][4][4];
    #pragma unroll
    for (int fm = 0; fm < 2; fm++)
        #pragma unroll
        for (int j = 0; j < 4; j++)
            #pragma unroll
            for (int e = 0; e < 4; e++) o[fm][j][e] = 0.f;
    float lacc[2][4] = {{0.f, 0.f, 0.f, 0.f}, {0.f, 0.f, 0.f, 0.f}};
    uint32_t bones = (lane < 4) ? 0x3C003C00u : 0u;

    __syncthreads();

    #pragma unroll 1
    for (int ch = 0; ch < 8; ch++) {     // 8 half-chunks of 32 cols
        int n0 = ch * 32;
        float s[2][4][4];
        #pragma unroll
        for (int fm = 0; fm < 2; fm++)
            #pragma unroll
            for (int nt = 0; nt < 4; nt++)
                #pragma unroll
                for (int e = 0; e < 4; e++) s[fm][nt][e] = 0.f;

        // S = Q K^T (32 x 32); K fragments shared by both m-tiles
        #pragma unroll
        for (int kt = 0; kt < 2; kt++) {
            #pragma unroll
            for (int nt = 0; nt < 4; nt++) {
                const __half* kp = &Ks[(n0 + nt * 8 + g) * LDK + kt * 16 + 2 * c];
                uint32_t b0 = *(const uint32_t*)kp;
                uint32_t b1 = *(const uint32_t*)(kp + 8);
                mma_f16(s[0][nt], qa[0][kt][0], qa[0][kt][1], qa[0][kt][2], qa[0][kt][3], b0, b1);
                mma_f16(s[1][nt], qa[1][kt][0], qa[1][kt][1], qa[1][kt][2], qa[1][kt][3], b0, b1);
            }
        }
        // p = 2^s; l via ones-MMA; PV with V fragments shared by both m-tiles
        #pragma unroll
        for (int kt2 = 0; kt2 < 2; kt2++) {
            uint32_t pa[2][4];
            #pragma unroll
            for (int fm = 0; fm < 2; fm++) {
                pa[fm][0] = ex2h2(packh2(s[fm][2 * kt2][0],     s[fm][2 * kt2][1]));
                pa[fm][1] = ex2h2(packh2(s[fm][2 * kt2][2],     s[fm][2 * kt2][3]));
                pa[fm][2] = ex2h2(packh2(s[fm][2 * kt2 + 1][0], s[fm][2 * kt2 + 1][1]));
                pa[fm][3] = ex2h2(packh2(s[fm][2 * kt2 + 1][2], s[fm][2 * kt2 + 1][3]));
                mma_f16(lacc[fm], pa[fm][0], pa[fm][1], pa[fm][2], pa[fm][3], bones, bones);
            }
            #pragma unroll
            for (int j = 0; j < 4; j++) {
                const __half* vp = &Vt[(j * 8 + g) * LDV + n0 + kt2 * 16 + 2 * c];
                uint32_t b0 = *(const uint32_t*)vp;
                uint32_t b1 = *(const uint32_t*)(vp + 8);
                mma_f16(o[0][j], pa[0][0], pa[0][1], pa[0][2], pa[0][3], b0, b1);
                mma_f16(o[1][j], pa[1][0], pa[1][1], pa[1][2], pa[1][3], b0, b1);
            }
        }
    }

    __half* Cp = g_ctx_h + (size_t)(bz >> 3) * (T * C) + (bz & 7) * HD;
    #pragma unroll
    for (int fm = 0; fm < 2; fm++) {
        float l0v = __shfl_sync(0xffffffffu, lacc[fm][0], lane & ~3);
        float l1v = __shfl_sync(0xffffffffu, lacc[fm][2], lane & ~3);
        float inv0 = 1.f / l0v, inv1 = 1.f / l1v;
        int r0 = t0r + fm * 16 + g;
        #pragma unroll
        for (int j = 0; j < 4; j++) {
            *(uint32_t*)&Cp[(size_t)r0       * C + j * 8 + 2 * c] =
                packh2(o[fm][j][0] * inv0, o[fm][j][1] * inv0);
            *(uint32_t*)&Cp[(size_t)(r0 + 8) * C + j * 8 + 2 * c] =
                packh2(o[fm][j][2] * inv1, o[fm][j][3] * inv1);
        }
    }
}

// ---------------- launcher ----------------
extern "C" void kernel_launch(void* const* d_in, const int* in_sizes, int n_in,
                              void* d_out, int out_size) {
    const float* x    = (const float*)d_in[0];
    const float* lnw  = (const float*)d_in[1];
    const float* lnb  = (const float*)d_in[2];
    const float* wqkv = (const float*)d_in[3];
    const float* bqkv = (const float*)d_in[4];
    const float* wout = (const float*)d_in[5];
    const float* bout = (const float*)d_in[6];
    float* out = (float*)d_out;

    constexpr int GEMM_SMEM  = 3 * 2 * 128 * 72 * 2;          // 110592
    constexpr int ATTN_SMEM  = (256 * 40 + 32 * 264) * 2;     // 37376
    constexpr int PN_SMEM    = 256 * 258 * 2 + 512 * 4;       // 134144

    static bool attr_done = false;
    if (!attr_done) {
        cudaFuncSetAttribute((const void*)k_qkv,
                             cudaFuncAttributeMaxDynamicSharedMemorySize, GEMM_SMEM);
        cudaFuncSetAttribute((const void*)k_outproj,
                             cudaFuncAttributeMaxDynamicSharedMemorySize, GEMM_SMEM);
        cudaFuncSetAttribute((const void*)k_attn3,
                             cudaFuncAttributeMaxDynamicSharedMemorySize, ATTN_SMEM);
        cudaFuncSetAttribute((const void*)k_pn,
                             cudaFuncAttributeMaxDynamicSharedMemorySize, PN_SMEM);
        attr_done = true;
    }

    k_cvtw<<<768, 256>>>(wqkv, wout);
    k_pn<<<NWIN, 256, PN_SMEM>>>(x, lnw, lnb);
    k_qkv<<<dim3(6, MTOK / 128), 256, GEMM_SMEM>>>(bqkv);
    k_attn3<<<NWIN * HEADS, 256, ATTN_SMEM>>>();
    k_outproj<<<dim3(2, MTOK / 128), 256, GEMM_SMEM>>>(bout, x, out);
}

// round 17
// speedup vs baseline: 1.1664x; 1.0175x over previous
#include <cuda_runtime.h>
#include <cuda_fp16.h>
#include <mma.h>
#include <math.h>
#include <cstdint>

using namespace nvcuda;

static constexpr int BATCH = 8;
static constexpr int C     = 256;
static constexpr int HH    = 128;
static constexpr int WWID  = 128;
static constexpr int NWIN  = 512;
static constexpr int T     = 256;
static constexpr int HEADS = 8;
static constexpr int HD    = 32;
static constexpr int MTOK  = NWIN * T;  // 131072

// ---------------- scratch ----------------
__device__ __align__(16) __half g_xn_h [(size_t)MTOK * C];
__device__ __align__(16) __half g_qh  [(size_t)MTOK * C];   // [win][h][t][e]
__device__ __align__(16) __half g_kh  [(size_t)MTOK * C];
__device__ __align__(16) __half g_vh  [(size_t)MTOK * C];
__device__ __align__(16) __half g_ctx_h[(size_t)MTOK * C];  // [win][t][h*32+e]
__device__ __align__(16) __half g_wqkv_h[768 * 256];
__device__ __align__(16) __half g_wout_h[256 * 256];

__device__ __forceinline__ uint32_t packh2(float lo, float hi) {
    __half2 h = __floats2half2_rn(lo, hi);
    return *reinterpret_cast<uint32_t*>(&h);
}
__device__ __forceinline__ uint32_t ex2h2(uint32_t a) {
    uint32_t d;
    asm("ex2.approx.f16x2 %0, %1;" : "=r"(d) : "r"(a));
    return d;
}
__device__ __forceinline__ uint32_t smem_u32(const void* p) {
    return (uint32_t)__cvta_generic_to_shared(p);
}
__device__ __forceinline__ void cp16(uint32_t dst, const void* src) {
    asm volatile("cp.async.cg.shared.global [%0], [%1], 16;" :: "r"(dst), "l"(src));
}
#define CP_COMMIT() asm volatile("cp.async.commit_group;")
#define CP_WAIT(n)  asm volatile("cp.async.wait_group %0;" :: "n"(n))

__device__ __forceinline__ void mma_f16(float* d,
        uint32_t a0, uint32_t a1, uint32_t a2, uint32_t a3,
        uint32_t b0, uint32_t b1) {
    asm volatile("mma.sync.aligned.m16n8k16.row.col.f32.f16.f16.f32 "
        "{%0,%1,%2,%3}, {%4,%5,%6,%7}, {%8,%9}, {%0,%1,%2,%3};"
        : "+f"(d[0]), "+f"(d[1]), "+f"(d[2]), "+f"(d[3])
        : "r"(a0), "r"(a1), "r"(a2), "r"(a3), "r"(b0), "r"(b1));
}
__device__ __forceinline__ void ldsm_x4(uint32_t* r, uint32_t addr) {
    asm volatile("ldmatrix.sync.aligned.m8n8.x4.shared.b16 {%0,%1,%2,%3}, [%4];"
        : "=r"(r[0]), "=r"(r[1]), "=r"(r[2]), "=r"(r[3]) : "r"(addr));
}

// ---------------- kernel 0: weight conversion ----------------
__global__ void k_cvtw(const float* __restrict__ wqkv, const float* __restrict__ wout) {
    int i = blockIdx.x * 256 + threadIdx.x;
    if (i < 768 * 256) g_wqkv_h[i] = __float2half(wqkv[i]);
    if (i < 256 * 256) g_wout_h[i] = __float2half(wout[i]);
}

// ---------------- kernel 1: fused partition + LN stats + normalize --------
__global__ __launch_bounds__(256) void k_pn(const float* __restrict__ x,
                                            const float* __restrict__ lw,
                                            const float* __restrict__ lb) {
    constexpr int LDX = 258;            // halves per row; 129 words (odd)
    extern __shared__ char smc[];
    __half*  xb  = (__half*)smc;                       // [256][258]
    __half2* xb2 = (__half2*)smc;
    float* smu = (float*)(smc + 256 * LDX * 2);
    float* srs = smu + 256;

    int tid = threadIdx.x;
    int n   = blockIdx.x;
    int b  = n >> 6;
    int wi = (n >> 3) & 7;
    int wj = n & 7;

    #pragma unroll
    for (int chunk = 0; chunk < 8; chunk++) {
        int c0 = chunk * 32;
        #pragma unroll
        for (int r = 0; r < 8; r++) {
            int rowid = r * 64 + (tid >> 2);
            int cl = rowid >> 4, ti = rowid & 15;
            int f4 = tid & 3;
            const float4* gp = (const float4*)(x
                + (size_t)((b * C + c0 + cl) * HH + wi * 16 + ti) * WWID
                + wj * 16) + f4;
            float4 v = *gp;
            int tb = ti * 16 + f4 * 4;
            xb[(tb + 0) * LDX + c0 + cl] = __float2half(v.x);
            xb[(tb + 1) * LDX + c0 + cl] = __float2half(v.y);
            xb[(tb + 2) * LDX + c0 + cl] = __float2half(v.z);
            xb[(tb + 3) * LDX + c0 + cl] = __float2half(v.w);
        }
    }
    __syncthreads();

    {
        int t = tid;
        float s = 0.f, s2 = 0.f;
        #pragma unroll 16
        for (int w = 0; w < 128; w++) {
            float2 f = __half22float2(xb2[t * 129 + w]);
            s += f.x + f.y;
            s2 += f.x * f.x + f.y * f.y;
        }
        float mu  = s * (1.f / C);
        float var = s2 * (1.f / C) - mu * mu;
        smu[t] = mu;
        srs[t] = rsqrtf(var + 1e-5f);
    }
    __syncthreads();

    #pragma unroll
    for (int pp = 0; pp < 8; pp++) {
        int t = pp * 32 + (tid >> 3);
        float mu = smu[t], rs = srs[t];
        #pragma unroll
        for (int i = 0; i < 8; i++) {
            int c = (tid & 7) * 4 + i * 32;
            int wbase = t * 129 + (c >> 1);
            float2 f0 = __half22float2(xb2[wbase]);
            float2 f1 = __half22float2(xb2[wbase + 1]);
            float4 w4 = *(const float4*)&lw[c];
            float4 b4 = *(const float4*)&lb[c];
            float o0 = (f0.x - mu) * rs * w4.x + b4.x;
            float o1 = (f0.y - mu) * rs * w4.y + b4.y;
            float o2 = (f1.x - mu) * rs * w4.z + b4.z;
            float o3 = (f1.y - mu) * rs * w4.w + b4.w;
            *(uint2*)&g_xn_h[((size_t)n * T + t) * C + c] =
                make_uint2(packh2(o0, o1), packh2(o2, o3));
        }
    }
}

// ---------------- kernel 2: QKV GEMM (raw mma + ldsm, register epilogue) --
__global__ __launch_bounds__(256, 2) void k_qkv(const float* __restrict__ bias) {
    constexpr int BM = 128, BK = 64, KDIM = 256;
    constexpr int NT = 256;
    constexpr int LDA = BK + 8;   // 72 halves
    constexpr int LDB = BK + 8;
    constexpr int ASTG = BM * LDA;
    constexpr int STG  = 2 * ASTG;
    constexpr int NS   = 3;
    constexpr int KT   = KDIM / BK;  // 4

    extern __shared__ __half smh[];

    int tid = threadIdx.x;
    int lane = tid & 31;
    int wi = tid >> 5;
    int wmi = wi & 1;       // 2 M-warps x 64 rows
    int wni = wi >> 1;      // 4 N-warps x 32 cols
    int m0 = blockIdx.y * BM;
    int n0 = blockIdx.x * 128;
    int g = lane >> 2, c = lane & 3;

    auto stageAB = [&](int kb, int s) {
        __half* As = smh + s * STG;
        __half* Bs = As + ASTG;
        #pragma unroll
        for (int r = 0; r < BM * BK / (NT * 8); r++) {
            int i = (r * NT + tid) * 8;
            int m = i / BK, k = i % BK;
            cp16(smem_u32(&As[m * LDA + k]), &g_xn_h[(size_t)(m0 + m) * KDIM + kb + k]);
        }
        #pragma unroll
        for (int r = 0; r < 128 * BK / (NT * 8); r++) {
            int i = (r * NT + tid) * 8;
            int n = i / BK, k = i % BK;
            cp16(smem_u32(&Bs[n * LDB + k]), &g_wqkv_h[(size_t)(n0 + n) * KDIM + kb + k]);
        }
    };

    float cf[4][4][4];
    #pragma unroll
    for (int fm = 0; fm < 4; fm++)
        #pragma unroll
        for (int nt = 0; nt < 4; nt++)
            #pragma unroll
            for (int e = 0; e < 4; e++) cf[fm][nt][e] = 0.f;

    stageAB(0, 0); CP_COMMIT();
    stageAB(BK, 1); CP_COMMIT();
    CP_WAIT(1);
    __syncthreads();

    int a_row = wmi * 64 + (lane & 15);
    int a_col = ((lane >> 4) & 1) * 8;
    int b_row = wni * 32 + ((lane >> 4) & 1) * 8 + (lane & 7);
    int b_col = ((lane >> 3) & 1) * 8;

    #pragma unroll
    for (int kbi = 0; kbi < KT; kbi++) {
        __half* As = smh + (kbi % NS) * STG;
        __half* Bs = As + ASTG;
        uint32_t a_base = smem_u32(As);
        uint32_t b_base = smem_u32(Bs);
        #pragma unroll
        for (int kk = 0; kk < 4; kk++) {
            uint32_t af[4][4];
            #pragma unroll
            for (int fm = 0; fm < 4; fm++)
                ldsm_x4(af[fm], a_base + 2 * ((a_row + fm * 16) * LDA + kk * 16 + a_col));
            uint32_t bf[4][2];
            #pragma unroll
            for (int bp = 0; bp < 2; bp++) {
                uint32_t tmp[4];
                ldsm_x4(tmp, b_base + 2 * ((b_row + bp * 16) * LDB + kk * 16 + b_col));
                bf[bp * 2][0] = tmp[0]; bf[bp * 2][1] = tmp[1];
                bf[bp * 2 + 1][0] = tmp[2]; bf[bp * 2 + 1][1] = tmp[3];
            }
            #pragma unroll
            for (int fm = 0; fm < 4; fm++)
                #pragma unroll
                for (int nt = 0; nt < 4; nt++)
                    mma_f16(cf[fm][nt], af[fm][0], af[fm][1], af[fm][2], af[fm][3],
                            bf[nt][0], bf[nt][1]);
        }
        if (kbi + NS - 1 < KT) {
            stageAB((kbi + NS - 1) * BK, (kbi + NS - 1) % NS);
            CP_COMMIT();
            CP_WAIT(1);
        } else {
            CP_WAIT(0);
        }
        __syncthreads();
    }

    #pragma unroll
    for (int nt = 0; nt < 4; nt++) {
        int col = n0 + wni * 32 + nt * 8 + 2 * c;
        float2 bb = *(const float2*)&bias[col];
        int part = col >> 8;
        int d = col & 255;
        int hh = d >> 5, e = d & 31;
        float scale = (part == 0) ? 0.25505697382625574f : 1.f;  // 1/sqrt(32)*log2e
        __half* dst = (part == 0) ? g_qh : (part == 1) ? g_kh : g_vh;
        #pragma unroll
        for (int fm = 0; fm < 4; fm++) {
            int r0 = m0 + wmi * 64 + fm * 16 + g;
            float v00 = (cf[fm][nt][0] + bb.x) * scale;
            float v01 = (cf[fm][nt][1] + bb.y) * scale;
            float v10 = (cf[fm][nt][2] + bb.x) * scale;
            float v11 = (cf[fm][nt][3] + bb.y) * scale;
            size_t o0 = ((size_t)((r0 >> 8) * HEADS + hh) * T + (r0 & 255)) * HD + e;
            size_t o1 = o0 + 8 * (size_t)HD;
            *(uint32_t*)&dst[o0] = packh2(v00, v01);
            *(uint32_t*)&dst[o1] = packh2(v10, v11);
        }
    }
}

// ---------------- kernel 3: out projection (wmma + L2 prefetch of x) ------
__global__ __launch_bounds__(256, 2) void k_outproj(const float* __restrict__ bias,
                                                    const float* __restrict__ x,
                                                    float* __restrict__ out) {
    constexpr int BM = 128, BN = 128, BK = 64, WM = 64, WN = 32, KDIM = 256;
    constexpr int WARPS_M = BM / WM;
    constexpr int NT = 256;
    constexpr int LDA = BK + 8;
    constexpr int LDB = BK + 8;
    constexpr int FM = WM / 16, FN = WN / 16;
    constexpr int ASTG = BM * LDA;
    constexpr int STG  = 2 * ASTG;
    constexpr int NS   = 3;
    constexpr int KT   = KDIM / BK;

    extern __shared__ float smf[];
    __half* smh = (__half*)smf;

    int tid = threadIdx.x;
    int m0 = blockIdx.y * BM;
    int n0 = blockIdx.x * BN;
    int wi = tid >> 5;
    int wmi = wi % WARPS_M;
    int wni = wi / WARPS_M;

    int n_win = m0 >> 8;
    int halfb = (m0 >> 7) & 1;
    int b  = n_win >> 6;
    int wr = (n_win >> 3) & 7;
    int wc = n_win & 7;

    wmma::fragment<wmma::accumulator, 16, 16, 16, float> cf[FM][FN];
    #pragma unroll
    for (int fm = 0; fm < FM; fm++)
        #pragma unroll
        for (int fn = 0; fn < FN; fn++)
            wmma::fill_fragment(cf[fm][fn], 0.f);

    auto stageAB = [&](int kb, int s) {
        __half* As = smh + s * STG;
        __half* Bs = As + ASTG;
        #pragma unroll
        for (int r = 0; r < BM * BK / (NT * 8); r++) {
            int i = (r * NT + tid) * 8;
            int m = i / BK, k = i % BK;
            cp16(smem_u32(&As[m * LDA + k]), &g_ctx_h[(size_t)(m0 + m) * KDIM + kb + k]);
        }
        #pragma unroll
        for (int r = 0; r < BN * BK / (NT * 8); r++) {
            int i = (r * NT + tid) * 8;
            int n = i / BK, k = i % BK;
            cp16(smem_u32(&Bs[n * LDB + k]), &g_wout_h[(size_t)(n0 + n) * KDIM + kb + k]);
        }
    };

    stageAB(0, 0); CP_COMMIT();
    stageAB(BK, 1); CP_COMMIT();

    // prefetch the residual x tile into L2 while GEMM runs
    #pragma unroll
    for (int r = 0; r < 4; r++) {
        int idx = r * 256 + tid;
        int cl = idx >> 3, ti = idx & 7;
        const float* pa = x + ((size_t)(b * C + n0 + cl) * HH + wr * 16 + halfb * 8 + ti) * WWID
                        + wc * 16;
        asm volatile("prefetch.global.L2 [%0];" :: "l"(pa));
    }

    CP_WAIT(1);
    __syncthreads();

    #pragma unroll
    for (int kbi = 0; kbi < KT; kbi++) {
        __half* As = smh + (kbi % NS) * STG;
        __half* Bs = As + ASTG;
        #pragma unroll
        for (int kk = 0; kk < BK; kk += 16) {
            wmma::fragment<wmma::matrix_a, 16, 16, 16, __half, wmma::row_major> af[FM];
            #pragma unroll
            for (int fm = 0; fm < FM; fm++)
                wmma::load_matrix_sync(af[fm], &As[(wmi * WM + fm * 16) * LDA + kk], LDA);
            #pragma unroll
            for (int fn = 0; fn < FN; fn++) {
                wmma::fragment<wmma::matrix_b, 16, 16, 16, __half, wmma::col_major> bf;
                wmma::load_matrix_sync(bf, &Bs[(wni * WN + fn * 16) * LDB + kk], LDB);
                #pragma unroll
                for (int fm = 0; fm < FM; fm++)
                    wmma::mma_sync(cf[fm][fn], af[fm], bf, cf[fm][fn]);
            }
        }
        if (kbi + NS - 1 < KT) {
            stageAB((kbi + NS - 1) * BK, (kbi + NS - 1) % NS);
            CP_COMMIT();
            CP_WAIT(1);
        } else {
            CP_WAIT(0);
        }
        __syncthreads();
    }

    constexpr int LDCT = BM + 4;
    float* Cs = smf;
    #pragma unroll
    for (int fm = 0; fm < FM; fm++)
        #pragma unroll
        for (int fn = 0; fn < FN; fn++)
            wmma::store_matrix_sync(&Cs[(wni * WN + fn * 16) * LDCT + wmi * WM + fm * 16],
                                    cf[fm][fn], LDCT, wmma::mem_col_major);
    __syncthreads();
    #pragma unroll
    for (int r = 0; r < BM * BN / (NT * 4); r++) {
        int idx = r * NT + tid;
        int f4 = idx & 3;
        int ti = (idx >> 2) & 7;
        int cl = idx >> 5;
        int gn = n0 + cl;
        int tok = ti * 16 + f4 * 4;
        float4 v = *(float4*)&Cs[cl * LDCT + tok];
        float bb = bias[gn];
        size_t off = ((size_t)(b * C + gn) * HH + wr * 16 + halfb * 8 + ti) * WWID
                   + wc * 16 + f4 * 4;
        float4 xr = *(const float4*)&x[off];
        float4 o_;
        o_.x = xr.x + v.x + bb;
        o_.y = xr.y + v.y + bb;
        o_.z = xr.z + v.z + bb;
        o_.w = xr.w + v.w + bb;
        *(float4*)&out[off] = o_;
    }
}

// ---------------- fused flash attention v4: 32 rows/warp + ldmatrix K/V ---
__global__ __launch_bounds__(256, 2) void k_attn3() {
    constexpr int LDK = 40;    // halves
    constexpr int LDV = 264;   // halves
    extern __shared__ __half smh[];
    __half* Ks = smh;                 // 256*40
    __half* Vt = smh + 256 * LDK;     // 32*264

    int bz = blockIdx.x;
    const __half* Q = g_qh + (size_t)bz * T * HD;
    const __half* K = g_kh + (size_t)bz * T * HD;
    const __half* V = g_vh + (size_t)bz * T * HD;
    int tid = threadIdx.x, wi = tid >> 5, lane = tid & 31;
    int g = lane >> 2, c = lane & 3;

    #pragma unroll
    for (int it = 0; it < 8; it++) {
        int i = it * 256 + tid;
        int row = i >> 3, c4 = (i & 7) * 4;
        *(uint2*)&Ks[row * LDK + c4] = *(const uint2*)&K[row * HD + c4];
        uint2 vv = *(const uint2*)&V[row * HD + c4];
        __half2 v01 = *reinterpret_cast<__half2*>(&vv.x);
        __half2 v23 = *reinterpret_cast<__half2*>(&vv.y);
        Vt[(c4 + 0) * LDV + row] = __low2half(v01);
        Vt[(c4 + 1) * LDV + row] = __high2half(v01);
        Vt[(c4 + 2) * LDV + row] = __low2half(v23);
        Vt[(c4 + 3) * LDV + row] = __high2half(v23);
    }

    int t0r = wi * 32;    // warp's first q row (32 rows per warp)

    uint32_t qa[2][2][4];
    #pragma unroll
    for (int fm = 0; fm < 2; fm++)
        #pragma unroll
        for (int kt = 0; kt < 2; kt++) {
            int r0 = t0r + fm * 16 + g;
            qa[fm][kt][0] = *(const uint32_t*)&Q[(size_t)r0       * HD + kt * 16 + 2 * c];
            qa[fm][kt][1] = *(const uint32_t*)&Q[(size_t)(r0 + 8) * HD + kt * 16 + 2 * c];
            qa[fm][kt][2] = *(const uint32_t*)&Q[(size_t)r0       * HD + kt * 16 + 2 * c + 8];
            qa[fm][kt][3] = *(const uint32_t*)&Q[(size_t)(r0 + 8) * HD + kt * 16 + 2 * c + 8];
        }

    float o[2][4][4];
    #pragma unroll
    for (int fm = 0; fm < 2; fm++)
        #pragma unroll
        for (int j = 0; j < 4; j++)
            #pragma unroll
            for (int e = 0; e < 4; e++) o[fm][j][e] = 0.f;
    float lacc[2][4] = {{0.f, 0.f, 0.f, 0.f}, {0.f, 0.f, 0.f, 0.f}};
    uint32_t bones = (lane < 4) ? 0x3C003C00u : 0u;

    // ldmatrix B-fragment lane geometry (row = n dim, col = k dim)
    int kr = ((lane >> 4) & 1) * 8 + (lane & 7);   // row within 16-row group
    int kc = ((lane >> 3) & 1) * 8;                // k-offset within 16

    __syncthreads();

    uint32_t ks_base = smem_u32(Ks);
    uint32_t vt_base = smem_u32(Vt);

    #pragma unroll 1
    for (int ch = 0; ch < 8; ch++) {     // 8 half-chunks of 32 cols
        int n0 = ch * 32;
        float s[2][4][4];
        #pragma unroll
        for (int fm = 0; fm < 2; fm++)
            #pragma unroll
            for (int nt = 0; nt < 4; nt++)
                #pragma unroll
                for (int e = 0; e < 4; e++) s[fm][nt][e] = 0.f;

        // S = Q K^T (32 x 32); K fragments via ldmatrix, shared by both m-tiles
        #pragma unroll
        for (int kt = 0; kt < 2; kt++) {
            uint32_t kb[4][2];
            #pragma unroll
            for (int ntp = 0; ntp < 2; ntp++) {
                uint32_t tmp[4];
                ldsm_x4(tmp, ks_base + 2 * ((n0 + ntp * 16 + kr) * LDK + kt * 16 + kc));
                kb[ntp * 2][0] = tmp[0]; kb[ntp * 2][1] = tmp[1];
                kb[ntp * 2 + 1][0] = tmp[2]; kb[ntp * 2 + 1][1] = tmp[3];
            }
            #pragma unroll
            for (int nt = 0; nt < 4; nt++) {
                mma_f16(s[0][nt], qa[0][kt][0], qa[0][kt][1], qa[0][kt][2], qa[0][kt][3],
                        kb[nt][0], kb[nt][1]);
                mma_f16(s[1][nt], qa[1][kt][0], qa[1][kt][1], qa[1][kt][2], qa[1][kt][3],
                        kb[nt][0], kb[nt][1]);
            }
        }
        // p = 2^s; l via ones-MMA; PV with V fragments via ldmatrix
        #pragma unroll
        for (int kt2 = 0; kt2 < 2; kt2++) {
            uint32_t pa[2][4];
            #pragma unroll
            for (int fm = 0; fm < 2; fm++) {
                pa[fm][0] = ex2h2(packh2(s[fm][2 * kt2][0],     s[fm][2 * kt2][1]));
                pa[fm][1] = ex2h2(packh2(s[fm][2 * kt2][2],     s[fm][2 * kt2][3]));
                pa[fm][2] = ex2h2(packh2(s[fm][2 * kt2 + 1][0], s[fm][2 * kt2 + 1][1]));
                pa[fm][3] = ex2h2(packh2(s[fm][2 * kt2 + 1][2], s[fm][2 * kt2 + 1][3]));
                mma_f16(lacc[fm], pa[fm][0], pa[fm][1], pa[fm][2], pa[fm][3], bones, bones);
            }
            uint32_t vb[4][2];
            #pragma unroll
            for (int jp = 0; jp < 2; jp++) {
                uint32_t tmp[4];
                ldsm_x4(tmp, vt_base + 2 * ((jp * 16 + kr) * LDV + n0 + kt2 * 16 + kc));
                vb[jp * 2][0] = tmp[0]; vb[jp * 2][1] = tmp[1];
                vb[jp * 2 + 1][0] = tmp[2]; vb[jp * 2 + 1][1] = tmp[3];
            }
            #pragma unroll
            for (int j = 0; j < 4; j++) {
                mma_f16(o[0][j], pa[0][0], pa[0][1], pa[0][2], pa[0][3], vb[j][0], vb[j][1]);
                mma_f16(o[1][j], pa[1][0], pa[1][1], pa[1][2], pa[1][3], vb[j][0], vb[j][1]);
            }
        }
    }

    __half* Cp = g_ctx_h + (size_t)(bz >> 3) * (T * C) + (bz & 7) * HD;
    #pragma unroll
    for (int fm = 0; fm < 2; fm++) {
        float l0v = __shfl_sync(0xffffffffu, lacc[fm][0], lane & ~3);
        float l1v = __shfl_sync(0xffffffffu, lacc[fm][2], lane & ~3);
        float inv0 = 1.f / l0v, inv1 = 1.f / l1v;
        int r0 = t0r + fm * 16 + g;
        #pragma unroll
        for (int j = 0; j < 4; j++) {
            *(uint32_t*)&Cp[(size_t)r0       * C + j * 8 + 2 * c] =
                packh2(o[fm][j][0] * inv0, o[fm][j][1] * inv0);
            *(uint32_t*)&Cp[(size_t)(r0 + 8) * C + j * 8 + 2 * c] =
                packh2(o[fm][j][2] * inv1, o[fm][j][3] * inv1);
        }
    }
}

// ---------------- launcher ----------------
extern "C" void kernel_launch(void* const* d_in, const int* in_sizes, int n_in,
                              void* d_out, int out_size) {
    const float* x    = (const float*)d_in[0];
    const float* lnw  = (const float*)d_in[1];
    const float* lnb  = (const float*)d_in[2];
    const float* wqkv = (const float*)d_in[3];
    const float* bqkv = (const float*)d_in[4];
    const float* wout = (const float*)d_in[5];
    const float* bout = (const float*)d_in[6];
    float* out = (float*)d_out;

    constexpr int GEMM_SMEM  = 3 * 2 * 128 * 72 * 2;          // 110592
    constexpr int ATTN_SMEM  = (256 * 40 + 32 * 264) * 2;     // 37376
    constexpr int PN_SMEM    = 256 * 258 * 2 + 512 * 4;       // 134144

    static bool attr_done = false;
    if (!attr_done) {
        cudaFuncSetAttribute((const void*)k_qkv,
                             cudaFuncAttributeMaxDynamicSharedMemorySize, GEMM_SMEM);
        cudaFuncSetAttribute((const void*)k_outproj,
                             cudaFuncAttributeMaxDynamicSharedMemorySize, GEMM_SMEM);
        cudaFuncSetAttribute((const void*)k_attn3,
                             cudaFuncAttributeMaxDynamicSharedMemorySize, ATTN_SMEM);
        cudaFuncSetAttribute((const void*)k_pn,
                             cudaFuncAttributeMaxDynamicSharedMemorySize, PN_SMEM);
        attr_done = true;
    }

    k_cvtw<<<768, 256>>>(wqkv, wout);
    k_pn<<<NWIN, 256, PN_SMEM>>>(x, lnw, lnb);
    k_qkv<<<dim3(6, MTOK / 128), 256, GEMM_SMEM>>>(bqkv);
    k_attn3<<<NWIN * HEADS, 256, ATTN_SMEM>>>();
    k_outproj<<<dim3(2, MTOK / 128), 256, GEMM_SMEM>>>(bout, x, out);
}